// round 12
// baseline (speedup 1.0000x reference)
#include <cuda_runtime.h>
#include <math.h>
#include <stdint.h>

#define BATCH   16
#define LSEQ    2048
#define DMODEL  256
#define DINNER  512
#define DSTATE  16
#define NOUT    256
#define NROWS   (BATCH*LSEQ)   /* 32768 */

// ---------------- device scratch (no allocations allowed) ----------------
__device__ float  g_xz[(size_t)NROWS * 1024];        // in_proj output (x | silu(z))
__device__ float  g_xc[(size_t)NROWS * DINNER];      // conv+silu output
__device__ float  g_xdbl[(size_t)NROWS * 128];       // x_proj output (48 used)
__device__ float  g_wxp[128 * DINNER];               // padded x_proj_w (48 rows)
__device__ float4 g_scanin[(size_t)NROWS * DINNER];  // (delta, delta*xc, silu(z), xc*D)
__device__ float2 g_bc[(size_t)NROWS * DSTATE];      // (B_n, C_n) interleaved
__device__ float  g_y[(size_t)NROWS * DINNER];       // scan output (pre out_proj)
__device__ float  g_t1[(size_t)NROWS * NOUT];        // silu(out_proj)
__device__ float  g_psum[512 * 2];                   // per-block (sum, sumsq)
__device__ float2 g_stats[BATCH];                    // (mean, rstd)

__device__ __forceinline__ float silu_f(float v) {
    return v / (1.f + __expf(-v));
}

// ---------------------------- bf16 helpers --------------------------------
__device__ __forceinline__ uint32_t pack_bf16x2(float hi, float lo) {
    uint32_t r;
    asm("cvt.rn.bf16x2.f32 %0, %1, %2;" : "=r"(r) : "f"(hi), "f"(lo));
    return r;
}
__device__ __forceinline__ float lo_f32(uint32_t p) {
    return __uint_as_float(p << 16);
}
__device__ __forceinline__ float hi_f32(uint32_t p) {
    return __uint_as_float(p & 0xffff0000u);
}
__device__ __forceinline__ void mma_bf16(float* c, const uint32_t* a,
                                         const uint32_t* b) {
    asm volatile(
        "mma.sync.aligned.m16n8k16.row.col.f32.bf16.bf16.f32 "
        "{%0,%1,%2,%3}, {%4,%5,%6,%7}, {%8,%9}, {%0,%1,%2,%3};"
        : "+f"(c[0]), "+f"(c[1]), "+f"(c[2]), "+f"(c[3])
        : "r"(a[0]), "r"(a[1]), "r"(a[2]), "r"(a[3]), "r"(b[0]), "r"(b[1]));
}

// -------------------- 3x-bf16 tensor-core NT GEMM (v2) --------------------
// cp.async 4-stage raw fp32 staging, double-buffered bf16-split smem.
// EPI: 0 = plain, 1 = silu, 2 = +bias + psum, 3 = silu on bn>=4 (z half)
#define KSTR 264
#define NSTAGE 4
#define RAW_F4   (NSTAGE * 512)
#define BUFN     (4 * KSTR)
#define GSM_BYTES (2 * RAW_F4 * 16 + 4 * 2 * BUFN * 4)  // 99328

template <int EPI>
__global__ void __launch_bounds__(256, 2)
gemm_bf16_kernel(const float* __restrict__ A, const float* __restrict__ B,
                 float* __restrict__ C, int N, int K,
                 const float* __restrict__ bias)
{
    extern __shared__ char sm[];
    float4*  rawA = (float4*)sm;
    float4*  rawB = rawA + RAW_F4;
    uint32_t* AhP = (uint32_t*)(rawB + RAW_F4);
    uint32_t* AlP = AhP + 2 * BUFN;
    uint32_t* BhP = AlP + 2 * BUFN;
    uint32_t* BlP = BhP + 2 * BUFN;
    __shared__ float red_s[256], red_ss[256];

    const int tid = threadIdx.x;
    const int wid = tid >> 5;
    const int lane = tid & 31;
    const int grp = lane >> 2;
    const int tg  = lane & 3;
    const int warp_m = wid & 1;
    const int warp_n = wid >> 1;
    const int bm = blockIdx.y, bn = blockIdx.x;

    const int lrow = tid >> 2;
    const int lkq  = tid & 3;

    const int k2a = lkq * 2, k2b = lkq * 2 + 1;
    const int sa_row = k2a & 3, sa_kh = k2a >> 2;
    const int sb_row = k2b & 3, sb_kh = k2b >> 2;

    const int nkt = K >> 4;
    const float* Ag = A + (size_t)(bm * 128 + lrow) * K + lkq * 4;
    const float* Bg = B + (size_t)(bn * 128 + lrow) * K + lkq * 4;
    const size_t rstep = (size_t)64 * K;

    float acc[4][4][4] = {};

#define GISSUE(ktv) do {                                                     \
    const int _kt = (ktv);                                                   \
    if (_kt < nkt) {                                                         \
        const int _s = _kt & (NSTAGE - 1);                                   \
        uint32_t _da0 = (uint32_t)__cvta_generic_to_shared(&rawA[_s*512 + tid]);     \
        uint32_t _da1 = (uint32_t)__cvta_generic_to_shared(&rawA[_s*512 + 256+tid]); \
        uint32_t _db0 = (uint32_t)__cvta_generic_to_shared(&rawB[_s*512 + tid]);     \
        uint32_t _db1 = (uint32_t)__cvta_generic_to_shared(&rawB[_s*512 + 256+tid]); \
        const float* _pa = Ag + _kt * 16;                                    \
        const float* _pb = Bg + _kt * 16;                                    \
        asm volatile("cp.async.cg.shared.global [%0], [%1], 16;"             \
                     :: "r"(_da0), "l"(_pa) : "memory");                     \
        asm volatile("cp.async.cg.shared.global [%0], [%1], 16;"             \
                     :: "r"(_da1), "l"(_pa + rstep) : "memory");             \
        asm volatile("cp.async.cg.shared.global [%0], [%1], 16;"             \
                     :: "r"(_db0), "l"(_pb) : "memory");                     \
        asm volatile("cp.async.cg.shared.global [%0], [%1], 16;"             \
                     :: "r"(_db1), "l"(_pb + rstep) : "memory");             \
    }                                                                        \
    asm volatile("cp.async.commit_group;" ::: "memory");                    \
} while (0)

    GISSUE(0); GISSUE(1); GISSUE(2);

    for (int kt = 0; kt < nkt; ++kt) {
        asm volatile("cp.async.wait_group %0;" :: "n"(2) : "memory");
        const int rs = kt & (NSTAGE - 1);
        const int bufo = (kt & 1) * BUFN;

#pragma unroll
        for (int rr = 0; rr < 2; ++rr) {
            const int r = lrow + rr * 64;
            float4 va = rawA[rs * 512 + rr * 256 + tid];
            float4 vb = rawB[rs * 512 + rr * 256 + tid];
            uint32_t h01 = pack_bf16x2(va.y, va.x);
            uint32_t h23 = pack_bf16x2(va.w, va.z);
            uint32_t l01 = pack_bf16x2(va.y - hi_f32(h01), va.x - lo_f32(h01));
            uint32_t l23 = pack_bf16x2(va.w - hi_f32(h23), va.z - lo_f32(h23));
            AhP[bufo + sa_row * KSTR + r * 2 + sa_kh] = h01;
            AlP[bufo + sa_row * KSTR + r * 2 + sa_kh] = l01;
            AhP[bufo + sb_row * KSTR + r * 2 + sb_kh] = h23;
            AlP[bufo + sb_row * KSTR + r * 2 + sb_kh] = l23;
            h01 = pack_bf16x2(vb.y, vb.x);
            h23 = pack_bf16x2(vb.w, vb.z);
            l01 = pack_bf16x2(vb.y - hi_f32(h01), vb.x - lo_f32(h01));
            l23 = pack_bf16x2(vb.w - hi_f32(h23), vb.z - lo_f32(h23));
            BhP[bufo + sa_row * KSTR + r * 2 + sa_kh] = h01;
            BlP[bufo + sa_row * KSTR + r * 2 + sa_kh] = l01;
            BhP[bufo + sb_row * KSTR + r * 2 + sb_kh] = h23;
            BlP[bufo + sb_row * KSTR + r * 2 + sb_kh] = l23;
        }

        GISSUE(kt + 3);
        __syncthreads();

        uint2 af[4][2], bh[4], bl[4];
#pragma unroll
        for (int mi = 0; mi < 4; ++mi) {
            const int m = warp_m * 64 + mi * 16 + grp;
            af[mi][0] = *(const uint2*)&AhP[bufo + tg * KSTR + 2 * m];
            af[mi][1] = *(const uint2*)&AhP[bufo + tg * KSTR + 2 * (m + 8)];
        }
#pragma unroll
        for (int ni = 0; ni < 4; ++ni) {
            const int n = warp_n * 32 + ni * 8 + grp;
            bh[ni] = *(const uint2*)&BhP[bufo + tg * KSTR + 2 * n];
            bl[ni] = *(const uint2*)&BlP[bufo + tg * KSTR + 2 * n];
        }
#pragma unroll
        for (int mi = 0; mi < 4; ++mi) {
            const uint32_t a[4] = {af[mi][0].x, af[mi][1].x,
                                   af[mi][0].y, af[mi][1].y};
#pragma unroll
            for (int ni = 0; ni < 4; ++ni) {
                const uint32_t b0[2] = {bh[ni].x, bh[ni].y};
                const uint32_t b1[2] = {bl[ni].x, bl[ni].y};
                mma_bf16(acc[mi][ni], a, b0);
                mma_bf16(acc[mi][ni], a, b1);
            }
        }
#pragma unroll
        for (int mi = 0; mi < 4; ++mi) {
            const int m = warp_m * 64 + mi * 16 + grp;
            af[mi][0] = *(const uint2*)&AlP[bufo + tg * KSTR + 2 * m];
            af[mi][1] = *(const uint2*)&AlP[bufo + tg * KSTR + 2 * (m + 8)];
        }
#pragma unroll
        for (int mi = 0; mi < 4; ++mi) {
            const uint32_t a[4] = {af[mi][0].x, af[mi][1].x,
                                   af[mi][0].y, af[mi][1].y};
#pragma unroll
            for (int ni = 0; ni < 4; ++ni) {
                const uint32_t b0[2] = {bh[ni].x, bh[ni].y};
                mma_bf16(acc[mi][ni], a, b0);
            }
        }
    }

    float s = 0.f, ss = 0.f;
    const bool dos = (EPI == 1) || (EPI == 3 && bn >= 4);
#pragma unroll
    for (int mi = 0; mi < 4; ++mi) {
        const int row0 = bm * 128 + warp_m * 64 + mi * 16 + grp;
#pragma unroll
        for (int ni = 0; ni < 4; ++ni) {
            const int col = bn * 128 + warp_n * 32 + ni * 8 + tg * 2;
            float v0 = acc[mi][ni][0], v1 = acc[mi][ni][1];
            float v2 = acc[mi][ni][2], v3 = acc[mi][ni][3];
            if (dos) { v0 = silu_f(v0); v1 = silu_f(v1);
                       v2 = silu_f(v2); v3 = silu_f(v3); }
            if (EPI == 2) {
                const float b0 = bias[col], b1 = bias[col + 1];
                v0 += b0; v1 += b1; v2 += b0; v3 += b1;
                s += v0 + v1 + v2 + v3;
                ss += v0 * v0 + v1 * v1 + v2 * v2 + v3 * v3;
            }
            *(float2*)(C + (size_t)row0 * N + col)       = make_float2(v0, v1);
            *(float2*)(C + (size_t)(row0 + 8) * N + col) = make_float2(v2, v3);
        }
    }

    if (EPI == 2) {
        red_s[tid] = s; red_ss[tid] = ss;
        __syncthreads();
        for (int off = 128; off > 0; off >>= 1) {
            if (tid < off) { red_s[tid] += red_s[tid + off];
                             red_ss[tid] += red_ss[tid + off]; }
            __syncthreads();
        }
        if (tid == 0) {
            int pid = bm * gridDim.x + bn;
            g_psum[2 * pid] = red_s[0];
            g_psum[2 * pid + 1] = red_ss[0];
        }
    }
}

// ---------------- causal depthwise conv + SiLU -> g_xc ---------------------
#define TOK 16
__global__ void __launch_bounds__(512)
conv_kernel(const float* __restrict__ conv_w, const float* __restrict__ conv_b)
{
    const int b  = blockIdx.x >> 7;
    const int l0 = (blockIdx.x & 127) * TOK;
    const int d  = threadIdx.x;

    float4 cw = ((const float4*)conv_w)[d];
    float cb = conv_b[d];
    const float* xcol = g_xz + (size_t)(b * 2048 + l0) * 1024 + d;
    float* ocol = g_xc + (size_t)(b * 2048 + l0) * 512 + d;
    float w0 = (l0 - 3 >= 0) ? xcol[-3 * 1024] : 0.f;
    float w1 = (l0 - 2 >= 0) ? xcol[-2 * 1024] : 0.f;
    float w2 = (l0 - 1 >= 0) ? xcol[-1 * 1024] : 0.f;
#pragma unroll
    for (int t = 0; t < TOK; ++t) {
        float cur = xcol[t * 1024];
        float acc = cb;
        acc = fmaf(w0, cw.x, acc);
        acc = fmaf(w1, cw.y, acc);
        acc = fmaf(w2, cw.z, acc);
        acc = fmaf(cur, cw.w, acc);
        ocol[(size_t)t * 512] = silu_f(acc);
        w0 = w1; w1 = w2; w2 = cur;
    }
}

// ---------------- pad x_proj_w into 128-row buffer --------------------------
__global__ void wpad_kernel(const float* __restrict__ x_proj_w)
{
    int i = blockIdx.x * 512 + threadIdx.x;
    if (i < 48 * 512) g_wxp[i] = x_proj_w[i];
    else if (i < 128 * 512) g_wxp[i] = 0.f;
}

// ---------------- dt_proj + softplus + scan-input pack ---------------------
__global__ void __launch_bounds__(512)
pack_kernel(const float* __restrict__ dt_proj_w, const float* __restrict__ dt_proj_b,
            const float* __restrict__ D_skip)
{
    const int b  = blockIdx.x >> 7;
    const int l0 = (blockIdx.x & 127) * TOK;
    const int d  = threadIdx.x;
    const int row0 = b * 2048 + l0;

    __shared__ float xdbl_s[TOK * 48];

    for (int i = d; i < TOK * 48; i += 512)
        xdbl_s[i] = g_xdbl[(size_t)(row0 + i / 48) * 128 + (i % 48)];
    __syncthreads();

    {
        const float4* dw = (const float4*)(dt_proj_w + d * 16);
        float4 dw0 = dw[0], dw1 = dw[1], dw2 = dw[2], dw3 = dw[3];
        const float dtb = dt_proj_b[d];
        const float Dv = D_skip[d];
        const float* zptr = g_xz + (size_t)row0 * 1024 + 512 + d;
        const float* xcptr = g_xc + (size_t)row0 * 512 + d;
        float4* outp = g_scanin + (size_t)row0 * 512 + d;
#pragma unroll
        for (int t = 0; t < TOK; ++t) {
            const float4* xr = (const float4*)&xdbl_s[t * 48];
            float4 x0 = xr[0], x1 = xr[1], x2 = xr[2], x3 = xr[3];
            float dt = dtb;
            dt = fmaf(x0.x, dw0.x, dt); dt = fmaf(x0.y, dw0.y, dt);
            dt = fmaf(x0.z, dw0.z, dt); dt = fmaf(x0.w, dw0.w, dt);
            dt = fmaf(x1.x, dw1.x, dt); dt = fmaf(x1.y, dw1.y, dt);
            dt = fmaf(x1.z, dw1.z, dt); dt = fmaf(x1.w, dw1.w, dt);
            dt = fmaf(x2.x, dw2.x, dt); dt = fmaf(x2.y, dw2.y, dt);
            dt = fmaf(x2.z, dw2.z, dt); dt = fmaf(x2.w, dw2.w, dt);
            dt = fmaf(x3.x, dw3.x, dt); dt = fmaf(x3.y, dw3.y, dt);
            dt = fmaf(x3.z, dw3.z, dt); dt = fmaf(x3.w, dw3.w, dt);
            float delta = (dt > 20.f) ? dt : __logf(1.f + __expf(dt));
            float xc = xcptr[(size_t)t * 512];
            float sz = zptr[(size_t)t * 1024];
            outp[(size_t)t * 512] = make_float4(delta, delta * xc, sz, xc * Dv);
        }
    }

    if (d < TOK * DSTATE) {
        const int t = d >> 4, n = d & 15;
        g_bc[(size_t)(row0 + t) * 16 + n] =
            make_float2(xdbl_s[t * 48 + 16 + n], xdbl_s[t * 48 + 32 + n]);
    }
}

// ---------------- diagonal selective scan (v5: cp.async pipeline) ---------
#define SDEPTH 4
__global__ void __launch_bounds__(128)
scan_kernel(const float* __restrict__ A_log)
{
    __shared__ float4 sv[4][SDEPTH][8][4];
    __shared__ float4 sbc[4][SDEPTH][8][8];

    const int wid = threadIdx.x >> 5;
    const int lane = threadIdx.x & 31;
    const int w = blockIdx.x * 4 + wid;
    const int b = w >> 7;
    const int dbase = (w & 127) * 4;
    const int li = lane & 7;
    const int dsub = lane >> 3;
    const int d = dbase + dsub;
    const int n0 = li * 2;

    const float LOG2E = 1.44269504f;
    const float An0 = -__expf(A_log[d * 16 + n0])     * LOG2E;
    const float An1 = -__expf(A_log[d * 16 + n0 + 1]) * LOG2E;

    const float4* vsrc  = g_scanin + (size_t)(b * 2048) * 512;
    const float4* bcsrc = reinterpret_cast<const float4*>(g_bc)
                          + (size_t)(b * 2048) * 8;
    float* yp = g_y + (size_t)(b * 2048) * 512 + d;

    const int lv_t = lane >> 2, lv_d = lane & 3;
    const int lb_t = lane >> 3, lb_q = lane & 7;

    float h0 = 0.f, h1 = 0.f;

#pragma unroll
    for (int s = 0; s < SDEPTH - 1; ++s) {
        const int tb = s * 8;
        uint32_t dv = (uint32_t)__cvta_generic_to_shared(&sv[wid][s][lv_t][lv_d]);
        const float4* pv = vsrc + (size_t)(tb + lv_t) * 512 + (dbase + lv_d);
        asm volatile("cp.async.cg.shared.global [%0], [%1], 16;"
                     :: "r"(dv), "l"(pv) : "memory");
        uint32_t db0 = (uint32_t)__cvta_generic_to_shared(&sbc[wid][s][lb_t][lb_q]);
        const float4* pb0 = bcsrc + (size_t)(tb + lb_t) * 8 + lb_q;
        asm volatile("cp.async.cg.shared.global [%0], [%1], 16;"
                     :: "r"(db0), "l"(pb0) : "memory");
        uint32_t db1 = (uint32_t)__cvta_generic_to_shared(&sbc[wid][s][lb_t + 4][lb_q]);
        const float4* pb1 = bcsrc + (size_t)(tb + lb_t + 4) * 8 + lb_q;
        asm volatile("cp.async.cg.shared.global [%0], [%1], 16;"
                     :: "r"(db1), "l"(pb1) : "memory");
        asm volatile("cp.async.commit_group;" ::: "memory");
    }

    for (int k = 0; k < 256; ++k) {
        asm volatile("cp.async.wait_group %0;" :: "n"(SDEPTH - 2) : "memory");
        __syncwarp();
        const int cs = k & (SDEPTH - 1);
#pragma unroll
        for (int j = 0; j < 8; ++j) {
            float4 v  = sv[wid][cs][j][dsub];
            float4 bc = sbc[wid][cs][j][li];
            float dA0 = exp2f(v.x * An0);
            float dA1 = exp2f(v.x * An1);
            h0 = fmaf(dA0, h0, v.y * bc.x);
            h1 = fmaf(dA1, h1, v.y * bc.z);
            float p = fmaf(h0, bc.y, h1 * bc.w);
            p += __shfl_xor_sync(0xffffffffu, p, 1);
            p += __shfl_xor_sync(0xffffffffu, p, 2);
            p += __shfl_xor_sync(0xffffffffu, p, 4);
            if (li == 0)
                yp[(size_t)(k * 8 + j) * 512] = (p + v.w) * v.z;
        }
        const int ks = k + SDEPTH - 1;
        if (ks < 256) {
            const int s = ks & (SDEPTH - 1);
            const int tb = ks * 8;
            uint32_t dv = (uint32_t)__cvta_generic_to_shared(&sv[wid][s][lv_t][lv_d]);
            const float4* pv = vsrc + (size_t)(tb + lv_t) * 512 + (dbase + lv_d);
            asm volatile("cp.async.cg.shared.global [%0], [%1], 16;"
                         :: "r"(dv), "l"(pv) : "memory");
            uint32_t db0 = (uint32_t)__cvta_generic_to_shared(&sbc[wid][s][lb_t][lb_q]);
            const float4* pb0 = bcsrc + (size_t)(tb + lb_t) * 8 + lb_q;
            asm volatile("cp.async.cg.shared.global [%0], [%1], 16;"
                         :: "r"(db0), "l"(pb0) : "memory");
            uint32_t db1 = (uint32_t)__cvta_generic_to_shared(&sbc[wid][s][lb_t + 4][lb_q]);
            const float4* pb1 = bcsrc + (size_t)(tb + lb_t + 4) * 8 + lb_q;
            asm volatile("cp.async.cg.shared.global [%0], [%1], 16;"
                         :: "r"(db1), "l"(pb1) : "memory");
        }
        asm volatile("cp.async.commit_group;" ::: "memory");
    }
}

// ------------------------- LayerNorm stats + apply ------------------------
__global__ void stats_kernel()
{
    int b = threadIdx.x;
    if (b >= BATCH) return;
    double s = 0.0, ss = 0.0;
    for (int bm = b * 16; bm < b * 16 + 16; ++bm)
        for (int bn = 0; bn < 2; ++bn) {
            int pid = bm * 2 + bn;
            s  += (double)g_psum[2 * pid];
            ss += (double)g_psum[2 * pid + 1];
        }
    const double nd = (double)LSEQ * NOUT;
    double mu = s / nd;
    double var = ss / nd - mu * mu;
    g_stats[b] = make_float2((float)mu, (float)rsqrt(var + 1e-5));
}

__global__ void __launch_bounds__(256)
norm_kernel(float* __restrict__ out, const float* __restrict__ lnw,
            const float* __restrict__ lnb)
{
    size_t i4 = (size_t)blockIdx.x * 256 + threadIdx.x;
    size_t base = i4 * 4;
    int row = (int)(base >> 8);
    int b = row >> 11;
    int l = row & 2047;
    int o = (int)(base & 255);
    float2 st = g_stats[b];
    float4 v = *(float4*)(out + base);
    const float4 w  = *(const float4*)(lnw + (size_t)l * 256 + o);
    const float4 bb = *(const float4*)(lnb + (size_t)l * 256 + o);
    v.x = (v.x - st.x) * st.y * w.x + bb.x;
    v.y = (v.y - st.x) * st.y * w.y + bb.y;
    v.z = (v.z - st.x) * st.y * w.z + bb.z;
    v.w = (v.w - st.x) * st.y * w.w + bb.w;
    *(float4*)(out + base) = v;
}

// ------------------------------- launch -----------------------------------
extern "C" void kernel_launch(void* const* d_in, const int* in_sizes, int n_in,
                              void* d_out, int out_size)
{
    const float* inputs    = (const float*)d_in[0];
    const float* in_proj_w = (const float*)d_in[1];
    const float* conv_w    = (const float*)d_in[2];
    const float* conv_b    = (const float*)d_in[3];
    const float* x_proj_w  = (const float*)d_in[4];
    const float* dt_proj_w = (const float*)d_in[5];
    const float* dt_proj_b = (const float*)d_in[6];
    const float* A_log     = (const float*)d_in[7];
    const float* D_skip    = (const float*)d_in[8];
    const float* out_proj_w= (const float*)d_in[9];
    const float* dim_w     = (const float*)d_in[10];
    const float* dim_b     = (const float*)d_in[11];
    const float* ln_w      = (const float*)d_in[12];
    const float* ln_b      = (const float*)d_in[13];
    float* out = (float*)d_out;

    float *xz, *y, *t1, *xc, *xdbl, *wxp;
    cudaGetSymbolAddress((void**)&xz,   g_xz);
    cudaGetSymbolAddress((void**)&y,    g_y);
    cudaGetSymbolAddress((void**)&t1,   g_t1);
    cudaGetSymbolAddress((void**)&xc,   g_xc);
    cudaGetSymbolAddress((void**)&xdbl, g_xdbl);
    cudaGetSymbolAddress((void**)&wxp,  g_wxp);

    cudaFuncSetAttribute(gemm_bf16_kernel<0>,
                         cudaFuncAttributeMaxDynamicSharedMemorySize, GSM_BYTES);
    cudaFuncSetAttribute(gemm_bf16_kernel<1>,
                         cudaFuncAttributeMaxDynamicSharedMemorySize, GSM_BYTES);
    cudaFuncSetAttribute(gemm_bf16_kernel<2>,
                         cudaFuncAttributeMaxDynamicSharedMemorySize, GSM_BYTES);
    cudaFuncSetAttribute(gemm_bf16_kernel<3>,
                         cudaFuncAttributeMaxDynamicSharedMemorySize, GSM_BYTES);

    // 0) pad x_proj_w -> g_wxp [128 x 512]
    wpad_kernel<<<128, 512>>>(x_proj_w);

    // 1) xz = inputs @ in_proj_w^T  [32768 x 1024], silu on z half (bn>=4)
    gemm_bf16_kernel<3><<<dim3(1024 / 128, NROWS / 128), 256, GSM_BYTES>>>(
        inputs, in_proj_w, xz, 1024, 256, nullptr);

    // 2a) causal conv + silu -> g_xc [32768 x 512]
    conv_kernel<<<NROWS / TOK, 512>>>(conv_w, conv_b);

    // 2b) x_dbl = xc @ wxp^T  [32768 x 128] (48 cols used)
    gemm_bf16_kernel<0><<<dim3(1, NROWS / 128), 256, GSM_BYTES>>>(
        xc, wxp, xdbl, 128, 512, nullptr);

    // 2c) dt_proj + softplus + pack scan inputs + bc
    pack_kernel<<<NROWS / TOK, 512>>>(dt_proj_w, dt_proj_b, D_skip);

    // 3) selective scan (v5: cp.async depth-4 pipeline)
    scan_kernel<<<512, 128>>>(A_log);

    // 4) t1 = silu(y @ out_proj_w^T)  [32768 x 256]
    gemm_bf16_kernel<1><<<dim3(256 / 128, NROWS / 128), 256, GSM_BYTES>>>(
        y, out_proj_w, t1, 256, 512, nullptr);

    // 5) out = t1 @ dim_w^T + dim_b, + per-block partial sums
    gemm_bf16_kernel<2><<<dim3(256 / 128, NROWS / 128), 256, GSM_BYTES>>>(
        t1, dim_w, out, 256, 256, dim_b);

    // 6) per-batch LayerNorm
    stats_kernel<<<1, 32>>>();
    norm_kernel<<<(NROWS * NOUT / 4) / 256, 256>>>(out, ln_w, ln_b);
}

// round 13
// speedup vs baseline: 1.4695x; 1.4695x over previous
#include <cuda_runtime.h>
#include <math.h>
#include <stdint.h>

#define BATCH   16
#define LSEQ    2048
#define DMODEL  256
#define DINNER  512
#define DSTATE  16
#define NOUT    256
#define NROWS   (BATCH*LSEQ)   /* 32768 */

// ---------------- device scratch (no allocations allowed) ----------------
__device__ float  g_xz[(size_t)NROWS * 1024];        // in_proj output (x | silu(z))
__device__ float4 g_scanin[(size_t)NROWS * DINNER];  // (delta, delta*xc, silu(z), xc*D)
__device__ float2 g_bc[(size_t)NROWS * DSTATE];      // (B_n, C_n) interleaved
__device__ float  g_y[(size_t)NROWS * DINNER];       // scan output (pre out_proj)
__device__ float  g_t1[(size_t)NROWS * NOUT];        // silu(out_proj)
__device__ float  g_psum[512 * 2];                   // per-block (sum, sumsq)
__device__ float2 g_stats[BATCH];                    // (mean, rstd)

// pre-split weight matrices, blocked fragment layout (1024 u32 per 128x16 tile)
__device__ uint4 g_w1h4[1024 * DMODEL / 8];
__device__ uint4 g_w1l4[1024 * DMODEL / 8];
__device__ uint4 g_w2h4[DMODEL * DINNER / 8];
__device__ uint4 g_w2l4[DMODEL * DINNER / 8];
__device__ uint4 g_w3h4[NOUT * DMODEL / 8];
__device__ uint4 g_w3l4[NOUT * DMODEL / 8];

__device__ __forceinline__ float silu_f(float v) {
    return v / (1.f + __expf(-v));
}

// ---------------------------- bf16 helpers --------------------------------
__device__ __forceinline__ uint32_t pack_bf16x2(float hi, float lo) {
    uint32_t r;
    asm("cvt.rn.bf16x2.f32 %0, %1, %2;" : "=r"(r) : "f"(hi), "f"(lo));
    return r;
}
__device__ __forceinline__ float lo_f32(uint32_t p) {
    return __uint_as_float(p << 16);
}
__device__ __forceinline__ float hi_f32(uint32_t p) {
    return __uint_as_float(p & 0xffff0000u);
}
__device__ __forceinline__ void mma_bf16(float* c, const uint32_t* a,
                                         const uint32_t* b) {
    asm volatile(
        "mma.sync.aligned.m16n8k16.row.col.f32.bf16.bf16.f32 "
        "{%0,%1,%2,%3}, {%4,%5,%6,%7}, {%8,%9}, {%0,%1,%2,%3};"
        : "+f"(c[0]), "+f"(c[1]), "+f"(c[2]), "+f"(c[3])
        : "r"(a[0]), "r"(a[1]), "r"(a[2]), "r"(a[3]), "r"(b[0]), "r"(b[1]));
}

// -------- fp32 [M x K] -> blocked-split bf16 hi/lo (round-10 proven) -------
// tile = 128 rows x 16 k; u32 offset in tile for (r, k2): (k2&3)*256+r*2+(k2>>2)
__global__ void __launch_bounds__(256)
split_blocked_kernel(const float* __restrict__ src, uint32_t* __restrict__ hi,
                     uint32_t* __restrict__ lo, int K)
{
    __shared__ float s[128][20];
    const int t = threadIdx.x;
    const int kt = blockIdx.x;
    const int rt = blockIdx.y;
    const float* sp = src + (size_t)rt * 128 * K + kt * 16;
#pragma unroll
    for (int i = 0; i < 2; ++i) {
        const int fi = t + i * 256;
        const int r = fi >> 2, kq = fi & 3;
        float4 v = *(const float4*)(sp + (size_t)r * K + kq * 4);
        *(float4*)&s[r][kq * 4] = v;
    }
    __syncthreads();
    const size_t tb = ((size_t)rt * gridDim.x + kt) << 10;
    const int r = t >> 1, kh = t & 1;
#pragma unroll
    for (int i = 0; i < 4; ++i) {
        const int k2 = kh * 4 + i;
        float f0 = s[r][2 * k2], f1 = s[r][2 * k2 + 1];
        uint32_t h = pack_bf16x2(f1, f0);
        uint32_t l = pack_bf16x2(f1 - hi_f32(h), f0 - lo_f32(h));
        hi[tb + i * 256 + t] = h;
        lo[tb + i * 256 + t] = l;
    }
}

// -------------------- 3x-bf16 tensor-core NT GEMM (v4) --------------------
// A: fp32, staged raw (4-stage cp.async) and converted in-kernel (round-11).
// B: pre-split blocked bf16 hi/lo, cp.async direct into padded fragment smem
//    (round-10 mechanics). Mainloop B conversion eliminated.
// EPI: 1 = silu, 2 = +bias + psum, 3 = silu on bn>=4 (z half)
#define KSTR 264
#define NSTAGE 4
#define RAW_F4   (NSTAGE * 512)              /* raw A: 4 stages x 8KB = 32KB */
#define ABUFN    (4 * KSTR)                  /* 1056 u32 per Ah/Al buffer */
#define OFF_AH   32768
#define OFF_AL   (32768 + 2 * ABUFN * 4)     /* 41216 */
#define OFF_BS   (OFF_AL + 2 * ABUFN * 4)    /* 49664 */
#define BSTAGE_B 8448                        /* hi 4224 + lo 4224 per stage */
#define GSM_BYTES (OFF_BS + NSTAGE * BSTAGE_B) /* 83456 */

template <int EPI>
__global__ void __launch_bounds__(256, 2)
gemm_bf16_kernel(const float* __restrict__ A,
                 const uint32_t* __restrict__ Bhg, const uint32_t* __restrict__ Blg,
                 float* __restrict__ C, int N, int K,
                 const float* __restrict__ bias)
{
    extern __shared__ char sm[];
    float4*   rawA = (float4*)sm;
    uint32_t* AhP  = (uint32_t*)(sm + OFF_AH);
    uint32_t* AlP  = (uint32_t*)(sm + OFF_AL);
    __shared__ float red_s[256], red_ss[256];

    const int tid = threadIdx.x;
    const int wid = tid >> 5;
    const int lane = tid & 31;
    const int grp = lane >> 2;
    const int tg  = lane & 3;
    const int warp_m = wid & 1;
    const int warp_n = wid >> 1;
    const int bm = blockIdx.y, bn = blockIdx.x;

    const int lrow = tid >> 2;
    const int lkq  = tid & 3;

    const int k2a = lkq * 2, k2b = lkq * 2 + 1;
    const int sa_row = k2a & 3, sa_kh = k2a >> 2;
    const int sb_row = k2b & 3, sb_kh = k2b >> 2;

    const int nkt = K >> 4;
    const float* Ag = A + (size_t)(bm * 128 + lrow) * K + lkq * 4;
    const size_t rstep = (size_t)64 * K;
    const int bdoff = (tid >> 6) * 1056 + (tid & 63) * 16;  // bytes, padded

    float acc[4][4][4] = {};

#define GISSUE(ktv) do {                                                     \
    const int _kt = (ktv);                                                   \
    if (_kt < nkt) {                                                         \
        const int _s = _kt & (NSTAGE - 1);                                   \
        uint32_t _da0 = (uint32_t)__cvta_generic_to_shared(&rawA[_s*512 + tid]);     \
        uint32_t _da1 = (uint32_t)__cvta_generic_to_shared(&rawA[_s*512 + 256+tid]); \
        const float* _pa = Ag + _kt * 16;                                    \
        asm volatile("cp.async.cg.shared.global [%0], [%1], 16;"             \
                     :: "r"(_da0), "l"(_pa) : "memory");                     \
        asm volatile("cp.async.cg.shared.global [%0], [%1], 16;"             \
                     :: "r"(_da1), "l"(_pa + rstep) : "memory");             \
        uint32_t _db = (uint32_t)__cvta_generic_to_shared(                   \
                           sm + OFF_BS + _s * BSTAGE_B + bdoff);             \
        const size_t _gb = (((size_t)bn * nkt + _kt) << 10) + tid * 4;       \
        asm volatile("cp.async.cg.shared.global [%0], [%1], 16;"             \
                     :: "r"(_db), "l"(Bhg + _gb) : "memory");                \
        asm volatile("cp.async.cg.shared.global [%0], [%1], 16;"             \
                     :: "r"(_db + 4224u), "l"(Blg + _gb) : "memory");        \
    }                                                                        \
    asm volatile("cp.async.commit_group;" ::: "memory");                    \
} while (0)

    GISSUE(0); GISSUE(1); GISSUE(2);

    for (int kt = 0; kt < nkt; ++kt) {
        asm volatile("cp.async.wait_group %0;" :: "n"(2) : "memory");
        const int rs = kt & (NSTAGE - 1);
        const int bufo = (kt & 1) * ABUFN;

        // A: thread-private raw readback -> bf16 split into double buffer
#pragma unroll
        for (int rr = 0; rr < 2; ++rr) {
            const int r = lrow + rr * 64;
            float4 va = rawA[rs * 512 + rr * 256 + tid];
            uint32_t h01 = pack_bf16x2(va.y, va.x);
            uint32_t h23 = pack_bf16x2(va.w, va.z);
            uint32_t l01 = pack_bf16x2(va.y - hi_f32(h01), va.x - lo_f32(h01));
            uint32_t l23 = pack_bf16x2(va.w - hi_f32(h23), va.z - lo_f32(h23));
            AhP[bufo + sa_row * KSTR + r * 2 + sa_kh] = h01;
            AlP[bufo + sa_row * KSTR + r * 2 + sa_kh] = l01;
            AhP[bufo + sb_row * KSTR + r * 2 + sb_kh] = h23;
            AlP[bufo + sb_row * KSTR + r * 2 + sb_kh] = l23;
        }

        __syncthreads();          // orders A writes AND closes prev B reads
        GISSUE(kt + 3);           // refills stage (kt-1)&3 — safe post-sync

        const uint32_t* Th = (const uint32_t*)(sm + OFF_BS + rs * BSTAGE_B);
        const uint32_t* Tl = Th + 1056;

        uint2 af[4][2], bh[4], bl[4];
#pragma unroll
        for (int mi = 0; mi < 4; ++mi) {
            const int m = warp_m * 64 + mi * 16 + grp;
            af[mi][0] = *(const uint2*)&AhP[bufo + tg * KSTR + 2 * m];
            af[mi][1] = *(const uint2*)&AhP[bufo + tg * KSTR + 2 * (m + 8)];
        }
#pragma unroll
        for (int ni = 0; ni < 4; ++ni) {
            const int n = warp_n * 32 + ni * 8 + grp;
            bh[ni] = *(const uint2*)&Th[tg * KSTR + 2 * n];
            bl[ni] = *(const uint2*)&Tl[tg * KSTR + 2 * n];
        }
#pragma unroll
        for (int mi = 0; mi < 4; ++mi) {
            const uint32_t a[4] = {af[mi][0].x, af[mi][1].x,
                                   af[mi][0].y, af[mi][1].y};
#pragma unroll
            for (int ni = 0; ni < 4; ++ni) {
                const uint32_t b0[2] = {bh[ni].x, bh[ni].y};
                const uint32_t b1[2] = {bl[ni].x, bl[ni].y};
                mma_bf16(acc[mi][ni], a, b0);
                mma_bf16(acc[mi][ni], a, b1);
            }
        }
#pragma unroll
        for (int mi = 0; mi < 4; ++mi) {
            const int m = warp_m * 64 + mi * 16 + grp;
            af[mi][0] = *(const uint2*)&AlP[bufo + tg * KSTR + 2 * m];
            af[mi][1] = *(const uint2*)&AlP[bufo + tg * KSTR + 2 * (m + 8)];
        }
#pragma unroll
        for (int mi = 0; mi < 4; ++mi) {
            const uint32_t a[4] = {af[mi][0].x, af[mi][1].x,
                                   af[mi][0].y, af[mi][1].y};
#pragma unroll
            for (int ni = 0; ni < 4; ++ni) {
                const uint32_t b0[2] = {bh[ni].x, bh[ni].y};
                mma_bf16(acc[mi][ni], a, b0);
            }
        }
    }

    float s = 0.f, ss = 0.f;
    const bool dos = (EPI == 1) || (EPI == 3 && bn >= 4);
#pragma unroll
    for (int mi = 0; mi < 4; ++mi) {
        const int row0 = bm * 128 + warp_m * 64 + mi * 16 + grp;
#pragma unroll
        for (int ni = 0; ni < 4; ++ni) {
            const int col = bn * 128 + warp_n * 32 + ni * 8 + tg * 2;
            float v0 = acc[mi][ni][0], v1 = acc[mi][ni][1];
            float v2 = acc[mi][ni][2], v3 = acc[mi][ni][3];
            if (dos) { v0 = silu_f(v0); v1 = silu_f(v1);
                       v2 = silu_f(v2); v3 = silu_f(v3); }
            if (EPI == 2) {
                const float b0 = bias[col], b1 = bias[col + 1];
                v0 += b0; v1 += b1; v2 += b0; v3 += b1;
                s += v0 + v1 + v2 + v3;
                ss += v0 * v0 + v1 * v1 + v2 * v2 + v3 * v3;
            }
            *(float2*)(C + (size_t)row0 * N + col)       = make_float2(v0, v1);
            *(float2*)(C + (size_t)(row0 + 8) * N + col) = make_float2(v2, v3);
        }
    }

    if (EPI == 2) {
        red_s[tid] = s; red_ss[tid] = ss;
        __syncthreads();
        for (int off = 128; off > 0; off >>= 1) {
            if (tid < off) { red_s[tid] += red_s[tid + off];
                             red_ss[tid] += red_ss[tid + off]; }
            __syncthreads();
        }
        if (tid == 0) {
            int pid = bm * gridDim.x + bn;
            g_psum[2 * pid] = red_s[0];
            g_psum[2 * pid + 1] = red_ss[0];
        }
    }
}

// ---------- fused causal conv + SiLU + x_proj + dt_proj + pack -----------
// (round-11 proven: __launch_bounds__(512,2) for 2 blocks/SM)
#define TOK 16
__global__ void __launch_bounds__(512, 2)
convproj_kernel(const float* __restrict__ conv_w, const float* __restrict__ conv_b,
                const float* __restrict__ x_proj_w, const float* __restrict__ dt_proj_w,
                const float* __restrict__ dt_proj_b, const float* __restrict__ D_skip)
{
    const int b  = blockIdx.x >> 7;
    const int l0 = (blockIdx.x & 127) * TOK;
    const int d  = threadIdx.x;

    __shared__ float xc_s[TOK][512];
    __shared__ float xdbl_s[TOK][48];

    {
        float4 cw = ((const float4*)conv_w)[d];
        float cb = conv_b[d];
        const float* xcol = g_xz + (size_t)(b * 2048 + l0) * 1024 + d;
        float w0 = (l0 - 3 >= 0) ? xcol[-3 * 1024] : 0.f;
        float w1 = (l0 - 2 >= 0) ? xcol[-2 * 1024] : 0.f;
        float w2 = (l0 - 1 >= 0) ? xcol[-1 * 1024] : 0.f;
#pragma unroll
        for (int t = 0; t < TOK; ++t) {
            float cur = xcol[t * 1024];
            float acc = cb;
            acc = fmaf(w0, cw.x, acc);
            acc = fmaf(w1, cw.y, acc);
            acc = fmaf(w2, cw.z, acc);
            acc = fmaf(cur, cw.w, acc);
            xc_s[t][d] = silu_f(acc);
            w0 = w1; w1 = w2; w2 = cur;
        }
    }
    __syncthreads();

    {
        const int warp = d >> 5, lane = d & 31;
        float4 wv[3][4];
        const float4* xw4 = (const float4*)x_proj_w;
#pragma unroll
        for (int jj = 0; jj < 3; ++jj) {
            const float4* wrow = xw4 + (size_t)(warp * 3 + jj) * 128;
#pragma unroll
            for (int q = 0; q < 4; ++q)
                wv[jj][q] = wrow[lane + q * 32];
        }
#pragma unroll
        for (int t = 0; t < TOK; ++t) {
            float4 xv[4];
            const float4* xr = (const float4*)&xc_s[t][0];
#pragma unroll
            for (int q = 0; q < 4; ++q) xv[q] = xr[lane + q * 32];
            float a0 = 0.f, a1 = 0.f, a2 = 0.f;
#pragma unroll
            for (int q = 0; q < 4; ++q) {
                a0 = fmaf(xv[q].x, wv[0][q].x, a0); a0 = fmaf(xv[q].y, wv[0][q].y, a0);
                a0 = fmaf(xv[q].z, wv[0][q].z, a0); a0 = fmaf(xv[q].w, wv[0][q].w, a0);
                a1 = fmaf(xv[q].x, wv[1][q].x, a1); a1 = fmaf(xv[q].y, wv[1][q].y, a1);
                a1 = fmaf(xv[q].z, wv[1][q].z, a1); a1 = fmaf(xv[q].w, wv[1][q].w, a1);
                a2 = fmaf(xv[q].x, wv[2][q].x, a2); a2 = fmaf(xv[q].y, wv[2][q].y, a2);
                a2 = fmaf(xv[q].z, wv[2][q].z, a2); a2 = fmaf(xv[q].w, wv[2][q].w, a2);
            }
#pragma unroll
            for (int off = 16; off; off >>= 1) {
                a0 += __shfl_xor_sync(0xffffffffu, a0, off);
                a1 += __shfl_xor_sync(0xffffffffu, a1, off);
                a2 += __shfl_xor_sync(0xffffffffu, a2, off);
            }
            if (lane == 0) {
                xdbl_s[t][warp * 3 + 0] = a0;
                xdbl_s[t][warp * 3 + 1] = a1;
                xdbl_s[t][warp * 3 + 2] = a2;
            }
        }
    }
    __syncthreads();

    {
        const float4* dw = (const float4*)(dt_proj_w + d * 16);
        float4 dw0 = dw[0], dw1 = dw[1], dw2 = dw[2], dw3 = dw[3];
        const float dtb = dt_proj_b[d];
        const float Dv = D_skip[d];
        const float* zptr = g_xz + (size_t)(b * 2048 + l0) * 1024 + 512 + d;
        float4* outp = g_scanin + (size_t)(b * 2048 + l0) * 512 + d;
#pragma unroll
        for (int t = 0; t < TOK; ++t) {
            const float4* xr = (const float4*)&xdbl_s[t][0];
            float4 x0 = xr[0], x1 = xr[1], x2 = xr[2], x3 = xr[3];
            float dt = dtb;
            dt = fmaf(x0.x, dw0.x, dt); dt = fmaf(x0.y, dw0.y, dt);
            dt = fmaf(x0.z, dw0.z, dt); dt = fmaf(x0.w, dw0.w, dt);
            dt = fmaf(x1.x, dw1.x, dt); dt = fmaf(x1.y, dw1.y, dt);
            dt = fmaf(x1.z, dw1.z, dt); dt = fmaf(x1.w, dw1.w, dt);
            dt = fmaf(x2.x, dw2.x, dt); dt = fmaf(x2.y, dw2.y, dt);
            dt = fmaf(x2.z, dw2.z, dt); dt = fmaf(x2.w, dw2.w, dt);
            dt = fmaf(x3.x, dw3.x, dt); dt = fmaf(x3.y, dw3.y, dt);
            dt = fmaf(x3.z, dw3.z, dt); dt = fmaf(x3.w, dw3.w, dt);
            float delta = (dt > 20.f) ? dt : __logf(1.f + __expf(dt));
            float xc = xc_s[t][d];
            float sz = zptr[(size_t)t * 1024];
            outp[(size_t)t * 512] = make_float4(delta, delta * xc, sz, xc * Dv);
        }
    }

    if (d < TOK * DSTATE) {
        const int t = d >> 4, n = d & 15;
        g_bc[(size_t)(b * 2048 + l0 + t) * 16 + n] =
            make_float2(xdbl_s[t][16 + n], xdbl_s[t][32 + n]);
    }
}

// ---------------- diagonal selective scan (v5: cp.async pipeline) ---------
#define SDEPTH 4
__global__ void __launch_bounds__(128)
scan_kernel(const float* __restrict__ A_log)
{
    __shared__ float4 sv[4][SDEPTH][8][4];
    __shared__ float4 sbc[4][SDEPTH][8][8];

    const int wid = threadIdx.x >> 5;
    const int lane = threadIdx.x & 31;
    const int w = blockIdx.x * 4 + wid;
    const int b = w >> 7;
    const int dbase = (w & 127) * 4;
    const int li = lane & 7;
    const int dsub = lane >> 3;
    const int d = dbase + dsub;
    const int n0 = li * 2;

    const float LOG2E = 1.44269504f;
    const float An0 = -__expf(A_log[d * 16 + n0])     * LOG2E;
    const float An1 = -__expf(A_log[d * 16 + n0 + 1]) * LOG2E;

    const float4* vsrc  = g_scanin + (size_t)(b * 2048) * 512;
    const float4* bcsrc = reinterpret_cast<const float4*>(g_bc)
                          + (size_t)(b * 2048) * 8;
    float* yp = g_y + (size_t)(b * 2048) * 512 + d;

    const int lv_t = lane >> 2, lv_d = lane & 3;
    const int lb_t = lane >> 3, lb_q = lane & 7;

    float h0 = 0.f, h1 = 0.f;

#pragma unroll
    for (int s = 0; s < SDEPTH - 1; ++s) {
        const int tb = s * 8;
        uint32_t dv = (uint32_t)__cvta_generic_to_shared(&sv[wid][s][lv_t][lv_d]);
        const float4* pv = vsrc + (size_t)(tb + lv_t) * 512 + (dbase + lv_d);
        asm volatile("cp.async.cg.shared.global [%0], [%1], 16;"
                     :: "r"(dv), "l"(pv) : "memory");
        uint32_t db0 = (uint32_t)__cvta_generic_to_shared(&sbc[wid][s][lb_t][lb_q]);
        const float4* pb0 = bcsrc + (size_t)(tb + lb_t) * 8 + lb_q;
        asm volatile("cp.async.cg.shared.global [%0], [%1], 16;"
                     :: "r"(db0), "l"(pb0) : "memory");
        uint32_t db1 = (uint32_t)__cvta_generic_to_shared(&sbc[wid][s][lb_t + 4][lb_q]);
        const float4* pb1 = bcsrc + (size_t)(tb + lb_t + 4) * 8 + lb_q;
        asm volatile("cp.async.cg.shared.global [%0], [%1], 16;"
                     :: "r"(db1), "l"(pb1) : "memory");
        asm volatile("cp.async.commit_group;" ::: "memory");
    }

    for (int k = 0; k < 256; ++k) {
        asm volatile("cp.async.wait_group %0;" :: "n"(SDEPTH - 2) : "memory");
        __syncwarp();
        const int cs = k & (SDEPTH - 1);
#pragma unroll
        for (int j = 0; j < 8; ++j) {
            float4 v  = sv[wid][cs][j][dsub];
            float4 bc = sbc[wid][cs][j][li];
            float dA0 = exp2f(v.x * An0);
            float dA1 = exp2f(v.x * An1);
            h0 = fmaf(dA0, h0, v.y * bc.x);
            h1 = fmaf(dA1, h1, v.y * bc.z);
            float p = fmaf(h0, bc.y, h1 * bc.w);
            p += __shfl_xor_sync(0xffffffffu, p, 1);
            p += __shfl_xor_sync(0xffffffffu, p, 2);
            p += __shfl_xor_sync(0xffffffffu, p, 4);
            if (li == 0)
                yp[(size_t)(k * 8 + j) * 512] = (p + v.w) * v.z;
        }
        const int ks = k + SDEPTH - 1;
        if (ks < 256) {
            const int s = ks & (SDEPTH - 1);
            const int tb = ks * 8;
            uint32_t dv = (uint32_t)__cvta_generic_to_shared(&sv[wid][s][lv_t][lv_d]);
            const float4* pv = vsrc + (size_t)(tb + lv_t) * 512 + (dbase + lv_d);
            asm volatile("cp.async.cg.shared.global [%0], [%1], 16;"
                         :: "r"(dv), "l"(pv) : "memory");
            uint32_t db0 = (uint32_t)__cvta_generic_to_shared(&sbc[wid][s][lb_t][lb_q]);
            const float4* pb0 = bcsrc + (size_t)(tb + lb_t) * 8 + lb_q;
            asm volatile("cp.async.cg.shared.global [%0], [%1], 16;"
                         :: "r"(db0), "l"(pb0) : "memory");
            uint32_t db1 = (uint32_t)__cvta_generic_to_shared(&sbc[wid][s][lb_t + 4][lb_q]);
            const float4* pb1 = bcsrc + (size_t)(tb + lb_t + 4) * 8 + lb_q;
            asm volatile("cp.async.cg.shared.global [%0], [%1], 16;"
                         :: "r"(db1), "l"(pb1) : "memory");
        }
        asm volatile("cp.async.commit_group;" ::: "memory");
    }
}

// ------------------------- LayerNorm stats + apply ------------------------
__global__ void stats_kernel()
{
    int b = threadIdx.x;
    if (b >= BATCH) return;
    double s = 0.0, ss = 0.0;
    for (int bm = b * 16; bm < b * 16 + 16; ++bm)
        for (int bn = 0; bn < 2; ++bn) {
            int pid = bm * 2 + bn;
            s  += (double)g_psum[2 * pid];
            ss += (double)g_psum[2 * pid + 1];
        }
    const double nd = (double)LSEQ * NOUT;
    double mu = s / nd;
    double var = ss / nd - mu * mu;
    g_stats[b] = make_float2((float)mu, (float)rsqrt(var + 1e-5));
}

__global__ void __launch_bounds__(256)
norm_kernel(float* __restrict__ out, const float* __restrict__ lnw,
            const float* __restrict__ lnb)
{
    size_t i4 = (size_t)blockIdx.x * 256 + threadIdx.x;
    size_t base = i4 * 4;
    int row = (int)(base >> 8);
    int b = row >> 11;
    int l = row & 2047;
    int o = (int)(base & 255);
    float2 st = g_stats[b];
    float4 v = *(float4*)(out + base);
    const float4 w  = *(const float4*)(lnw + (size_t)l * 256 + o);
    const float4 bb = *(const float4*)(lnb + (size_t)l * 256 + o);
    v.x = (v.x - st.x) * st.y * w.x + bb.x;
    v.y = (v.y - st.x) * st.y * w.y + bb.y;
    v.z = (v.z - st.x) * st.y * w.z + bb.z;
    v.w = (v.w - st.x) * st.y * w.w + bb.w;
    *(float4*)(out + base) = v;
}

// ------------------------------- launch -----------------------------------
extern "C" void kernel_launch(void* const* d_in, const int* in_sizes, int n_in,
                              void* d_out, int out_size)
{
    const float* inputs    = (const float*)d_in[0];
    const float* in_proj_w = (const float*)d_in[1];
    const float* conv_w    = (const float*)d_in[2];
    const float* conv_b    = (const float*)d_in[3];
    const float* x_proj_w  = (const float*)d_in[4];
    const float* dt_proj_w = (const float*)d_in[5];
    const float* dt_proj_b = (const float*)d_in[6];
    const float* A_log     = (const float*)d_in[7];
    const float* D_skip    = (const float*)d_in[8];
    const float* out_proj_w= (const float*)d_in[9];
    const float* dim_w     = (const float*)d_in[10];
    const float* dim_b     = (const float*)d_in[11];
    const float* ln_w      = (const float*)d_in[12];
    const float* ln_b      = (const float*)d_in[13];
    float* out = (float*)d_out;

    float *xz, *y, *t1;
    cudaGetSymbolAddress((void**)&xz, g_xz);
    cudaGetSymbolAddress((void**)&y,  g_y);
    cudaGetSymbolAddress((void**)&t1, g_t1);
    uint32_t *w1h, *w1l, *w2h, *w2l, *w3h, *w3l;
    cudaGetSymbolAddress((void**)&w1h, g_w1h4);
    cudaGetSymbolAddress((void**)&w1l, g_w1l4);
    cudaGetSymbolAddress((void**)&w2h, g_w2h4);
    cudaGetSymbolAddress((void**)&w2l, g_w2l4);
    cudaGetSymbolAddress((void**)&w3h, g_w3h4);
    cudaGetSymbolAddress((void**)&w3l, g_w3l4);

    cudaFuncSetAttribute(gemm_bf16_kernel<1>,
                         cudaFuncAttributeMaxDynamicSharedMemorySize, GSM_BYTES);
    cudaFuncSetAttribute(gemm_bf16_kernel<2>,
                         cudaFuncAttributeMaxDynamicSharedMemorySize, GSM_BYTES);
    cudaFuncSetAttribute(gemm_bf16_kernel<3>,
                         cudaFuncAttributeMaxDynamicSharedMemorySize, GSM_BYTES);

    // 0) pre-split the three weight matrices into blocked fragment layout
    split_blocked_kernel<<<dim3(DMODEL / 16, 1024 / 128), 256>>>(
        in_proj_w, w1h, w1l, DMODEL);
    split_blocked_kernel<<<dim3(DINNER / 16, DMODEL / 128), 256>>>(
        out_proj_w, w2h, w2l, DINNER);
    split_blocked_kernel<<<dim3(DMODEL / 16, NOUT / 128), 256>>>(
        dim_w, w3h, w3l, DMODEL);

    // 1) xz = inputs @ in_proj_w^T  [32768 x 1024], silu on z half (bn>=4)
    gemm_bf16_kernel<3><<<dim3(1024 / 128, NROWS / 128), 256, GSM_BYTES>>>(
        inputs, w1h, w1l, xz, 1024, 256, nullptr);

    // 2) conv + silu + x_proj + dt_proj, packed scan inputs
    convproj_kernel<<<NROWS / TOK, 512>>>(conv_w, conv_b, x_proj_w,
                                          dt_proj_w, dt_proj_b, D_skip);

    // 3) selective scan (v5: cp.async depth-4 pipeline)
    scan_kernel<<<512, 128>>>(A_log);

    // 4) t1 = silu(y @ out_proj_w^T)  [32768 x 256]
    gemm_bf16_kernel<1><<<dim3(256 / 128, NROWS / 128), 256, GSM_BYTES>>>(
        y, w2h, w2l, t1, 256, 512, nullptr);

    // 5) out = t1 @ dim_w^T + dim_b, + per-block partial sums
    gemm_bf16_kernel<2><<<dim3(256 / 128, NROWS / 128), 256, GSM_BYTES>>>(
        t1, w3h, w3l, out, 256, 256, dim_b);

    // 6) per-batch LayerNorm
    stats_kernel<<<1, 32>>>();
    norm_kernel<<<(NROWS * NOUT / 4) / 256, 256>>>(out, ln_w, ln_b);
}

// round 14
// speedup vs baseline: 1.4763x; 1.0046x over previous
#include <cuda_runtime.h>
#include <math.h>
#include <stdint.h>

#define BATCH   16
#define LSEQ    2048
#define DMODEL  256
#define DINNER  512
#define DSTATE  16
#define NOUT    256
#define NROWS   (BATCH*LSEQ)   /* 32768 */

// ---------------- device scratch (no allocations allowed) ----------------
__device__ float  g_xz[(size_t)NROWS * 1024];        // in_proj output (x | silu(z))
__device__ float4 g_scanin[(size_t)NROWS * DINNER];  // (delta, delta*xc, silu(z), xc*D)
__device__ float2 g_bc[(size_t)NROWS * DSTATE];      // (B_n, C_n) interleaved
__device__ float  g_y[(size_t)NROWS * DINNER];       // scan output (pre out_proj)
__device__ float  g_t1[(size_t)NROWS * NOUT];        // silu(out_proj)
__device__ float  g_psum[512 * 2];                   // per-block (sum, sumsq)
__device__ float2 g_stats[BATCH];                    // (mean, rstd)

// pre-split weight matrices, blocked fragment layout (1024 u32 per 128x16 tile)
__device__ uint4 g_w1h4[1024 * DMODEL / 8];
__device__ uint4 g_w1l4[1024 * DMODEL / 8];
__device__ uint4 g_w2h4[DMODEL * DINNER / 8];
__device__ uint4 g_w2l4[DMODEL * DINNER / 8];
__device__ uint4 g_w3h4[NOUT * DMODEL / 8];
__device__ uint4 g_w3l4[NOUT * DMODEL / 8];

__device__ __forceinline__ float silu_f(float v) {
    return v / (1.f + __expf(-v));
}

// ---------------------------- bf16 helpers --------------------------------
__device__ __forceinline__ uint32_t pack_bf16x2(float hi, float lo) {
    uint32_t r;
    asm("cvt.rn.bf16x2.f32 %0, %1, %2;" : "=r"(r) : "f"(hi), "f"(lo));
    return r;
}
__device__ __forceinline__ float lo_f32(uint32_t p) {
    return __uint_as_float(p << 16);
}
__device__ __forceinline__ float hi_f32(uint32_t p) {
    return __uint_as_float(p & 0xffff0000u);
}
__device__ __forceinline__ void mma_bf16(float* c, const uint32_t* a,
                                         const uint32_t* b) {
    asm volatile(
        "mma.sync.aligned.m16n8k16.row.col.f32.bf16.bf16.f32 "
        "{%0,%1,%2,%3}, {%4,%5,%6,%7}, {%8,%9}, {%0,%1,%2,%3};"
        : "+f"(c[0]), "+f"(c[1]), "+f"(c[2]), "+f"(c[3])
        : "r"(a[0]), "r"(a[1]), "r"(a[2]), "r"(a[3]), "r"(b[0]), "r"(b[1]));
}

// -------- fp32 [M x K] -> blocked-split bf16 hi/lo (round-10 proven) -------
__global__ void __launch_bounds__(256)
split_blocked_kernel(const float* __restrict__ src, uint32_t* __restrict__ hi,
                     uint32_t* __restrict__ lo, int K)
{
    __shared__ float s[128][20];
    const int t = threadIdx.x;
    const int kt = blockIdx.x;
    const int rt = blockIdx.y;
    const float* sp = src + (size_t)rt * 128 * K + kt * 16;
#pragma unroll
    for (int i = 0; i < 2; ++i) {
        const int fi = t + i * 256;
        const int r = fi >> 2, kq = fi & 3;
        float4 v = *(const float4*)(sp + (size_t)r * K + kq * 4);
        *(float4*)&s[r][kq * 4] = v;
    }
    __syncthreads();
    const size_t tb = ((size_t)rt * gridDim.x + kt) << 10;
    const int r = t >> 1, kh = t & 1;
#pragma unroll
    for (int i = 0; i < 4; ++i) {
        const int k2 = kh * 4 + i;
        float f0 = s[r][2 * k2], f1 = s[r][2 * k2 + 1];
        uint32_t h = pack_bf16x2(f1, f0);
        uint32_t l = pack_bf16x2(f1 - hi_f32(h), f0 - lo_f32(h));
        hi[tb + i * 256 + t] = h;
        lo[tb + i * 256 + t] = l;
    }
}

// -------------------- 3x-bf16 tensor-core NT GEMM (v4) --------------------
#define KSTR 264
#define NSTAGE 4
#define RAW_F4   (NSTAGE * 512)
#define ABUFN    (4 * KSTR)
#define OFF_AH   32768
#define OFF_AL   (32768 + 2 * ABUFN * 4)
#define OFF_BS   (OFF_AL + 2 * ABUFN * 4)
#define BSTAGE_B 8448
#define GSM_BYTES (OFF_BS + NSTAGE * BSTAGE_B) /* 83456 */

template <int EPI>
__global__ void __launch_bounds__(256, 2)
gemm_bf16_kernel(const float* __restrict__ A,
                 const uint32_t* __restrict__ Bhg, const uint32_t* __restrict__ Blg,
                 float* __restrict__ C, int N, int K,
                 const float* __restrict__ bias)
{
    extern __shared__ char sm[];
    float4*   rawA = (float4*)sm;
    uint32_t* AhP  = (uint32_t*)(sm + OFF_AH);
    uint32_t* AlP  = (uint32_t*)(sm + OFF_AL);
    __shared__ float red_s[256], red_ss[256];

    const int tid = threadIdx.x;
    const int wid = tid >> 5;
    const int lane = tid & 31;
    const int grp = lane >> 2;
    const int tg  = lane & 3;
    const int warp_m = wid & 1;
    const int warp_n = wid >> 1;
    const int bm = blockIdx.y, bn = blockIdx.x;

    const int lrow = tid >> 2;
    const int lkq  = tid & 3;

    const int k2a = lkq * 2, k2b = lkq * 2 + 1;
    const int sa_row = k2a & 3, sa_kh = k2a >> 2;
    const int sb_row = k2b & 3, sb_kh = k2b >> 2;

    const int nkt = K >> 4;
    const float* Ag = A + (size_t)(bm * 128 + lrow) * K + lkq * 4;
    const size_t rstep = (size_t)64 * K;
    const int bdoff = (tid >> 6) * 1056 + (tid & 63) * 16;

    float acc[4][4][4] = {};

#define GISSUE(ktv) do {                                                     \
    const int _kt = (ktv);                                                   \
    if (_kt < nkt) {                                                         \
        const int _s = _kt & (NSTAGE - 1);                                   \
        uint32_t _da0 = (uint32_t)__cvta_generic_to_shared(&rawA[_s*512 + tid]);     \
        uint32_t _da1 = (uint32_t)__cvta_generic_to_shared(&rawA[_s*512 + 256+tid]); \
        const float* _pa = Ag + _kt * 16;                                    \
        asm volatile("cp.async.cg.shared.global [%0], [%1], 16;"             \
                     :: "r"(_da0), "l"(_pa) : "memory");                     \
        asm volatile("cp.async.cg.shared.global [%0], [%1], 16;"             \
                     :: "r"(_da1), "l"(_pa + rstep) : "memory");             \
        uint32_t _db = (uint32_t)__cvta_generic_to_shared(                   \
                           sm + OFF_BS + _s * BSTAGE_B + bdoff);             \
        const size_t _gb = (((size_t)bn * nkt + _kt) << 10) + tid * 4;       \
        asm volatile("cp.async.cg.shared.global [%0], [%1], 16;"             \
                     :: "r"(_db), "l"(Bhg + _gb) : "memory");                \
        asm volatile("cp.async.cg.shared.global [%0], [%1], 16;"             \
                     :: "r"(_db + 4224u), "l"(Blg + _gb) : "memory");        \
    }                                                                        \
    asm volatile("cp.async.commit_group;" ::: "memory");                    \
} while (0)

    GISSUE(0); GISSUE(1); GISSUE(2);

    for (int kt = 0; kt < nkt; ++kt) {
        asm volatile("cp.async.wait_group %0;" :: "n"(2) : "memory");
        const int rs = kt & (NSTAGE - 1);
        const int bufo = (kt & 1) * ABUFN;

#pragma unroll
        for (int rr = 0; rr < 2; ++rr) {
            const int r = lrow + rr * 64;
            float4 va = rawA[rs * 512 + rr * 256 + tid];
            uint32_t h01 = pack_bf16x2(va.y, va.x);
            uint32_t h23 = pack_bf16x2(va.w, va.z);
            uint32_t l01 = pack_bf16x2(va.y - hi_f32(h01), va.x - lo_f32(h01));
            uint32_t l23 = pack_bf16x2(va.w - hi_f32(h23), va.z - lo_f32(h23));
            AhP[bufo + sa_row * KSTR + r * 2 + sa_kh] = h01;
            AlP[bufo + sa_row * KSTR + r * 2 + sa_kh] = l01;
            AhP[bufo + sb_row * KSTR + r * 2 + sb_kh] = h23;
            AlP[bufo + sb_row * KSTR + r * 2 + sb_kh] = l23;
        }

        __syncthreads();
        GISSUE(kt + 3);

        const uint32_t* Th = (const uint32_t*)(sm + OFF_BS + rs * BSTAGE_B);
        const uint32_t* Tl = Th + 1056;

        uint2 af[4][2], bh[4], bl[4];
#pragma unroll
        for (int mi = 0; mi < 4; ++mi) {
            const int m = warp_m * 64 + mi * 16 + grp;
            af[mi][0] = *(const uint2*)&AhP[bufo + tg * KSTR + 2 * m];
            af[mi][1] = *(const uint2*)&AhP[bufo + tg * KSTR + 2 * (m + 8)];
        }
#pragma unroll
        for (int ni = 0; ni < 4; ++ni) {
            const int n = warp_n * 32 + ni * 8 + grp;
            bh[ni] = *(const uint2*)&Th[tg * KSTR + 2 * n];
            bl[ni] = *(const uint2*)&Tl[tg * KSTR + 2 * n];
        }
#pragma unroll
        for (int mi = 0; mi < 4; ++mi) {
            const uint32_t a[4] = {af[mi][0].x, af[mi][1].x,
                                   af[mi][0].y, af[mi][1].y};
#pragma unroll
            for (int ni = 0; ni < 4; ++ni) {
                const uint32_t b0[2] = {bh[ni].x, bh[ni].y};
                const uint32_t b1[2] = {bl[ni].x, bl[ni].y};
                mma_bf16(acc[mi][ni], a, b0);
                mma_bf16(acc[mi][ni], a, b1);
            }
        }
#pragma unroll
        for (int mi = 0; mi < 4; ++mi) {
            const int m = warp_m * 64 + mi * 16 + grp;
            af[mi][0] = *(const uint2*)&AlP[bufo + tg * KSTR + 2 * m];
            af[mi][1] = *(const uint2*)&AlP[bufo + tg * KSTR + 2 * (m + 8)];
        }
#pragma unroll
        for (int mi = 0; mi < 4; ++mi) {
            const uint32_t a[4] = {af[mi][0].x, af[mi][1].x,
                                   af[mi][0].y, af[mi][1].y};
#pragma unroll
            for (int ni = 0; ni < 4; ++ni) {
                const uint32_t b0[2] = {bh[ni].x, bh[ni].y};
                mma_bf16(acc[mi][ni], a, b0);
            }
        }
    }

    float s = 0.f, ss = 0.f;
    const bool dos = (EPI == 1) || (EPI == 3 && bn >= 4);
#pragma unroll
    for (int mi = 0; mi < 4; ++mi) {
        const int row0 = bm * 128 + warp_m * 64 + mi * 16 + grp;
#pragma unroll
        for (int ni = 0; ni < 4; ++ni) {
            const int col = bn * 128 + warp_n * 32 + ni * 8 + tg * 2;
            float v0 = acc[mi][ni][0], v1 = acc[mi][ni][1];
            float v2 = acc[mi][ni][2], v3 = acc[mi][ni][3];
            if (dos) { v0 = silu_f(v0); v1 = silu_f(v1);
                       v2 = silu_f(v2); v3 = silu_f(v3); }
            if (EPI == 2) {
                const float b0 = bias[col], b1 = bias[col + 1];
                v0 += b0; v1 += b1; v2 += b0; v3 += b1;
                s += v0 + v1 + v2 + v3;
                ss += v0 * v0 + v1 * v1 + v2 * v2 + v3 * v3;
            }
            *(float2*)(C + (size_t)row0 * N + col)       = make_float2(v0, v1);
            *(float2*)(C + (size_t)(row0 + 8) * N + col) = make_float2(v2, v3);
        }
    }

    if (EPI == 2) {
        red_s[tid] = s; red_ss[tid] = ss;
        __syncthreads();
        for (int off = 128; off > 0; off >>= 1) {
            if (tid < off) { red_s[tid] += red_s[tid + off];
                             red_ss[tid] += red_ss[tid + off]; }
            __syncthreads();
        }
        if (tid == 0) {
            int pid = bm * gridDim.x + bn;
            g_psum[2 * pid] = red_s[0];
            g_psum[2 * pid + 1] = red_ss[0];
        }
    }
}

// ---------- fused causal conv + SiLU + x_proj + dt_proj + pack -----------
#define TOK 16
__global__ void __launch_bounds__(512, 2)
convproj_kernel(const float* __restrict__ conv_w, const float* __restrict__ conv_b,
                const float* __restrict__ x_proj_w, const float* __restrict__ dt_proj_w,
                const float* __restrict__ dt_proj_b, const float* __restrict__ D_skip)
{
    const int b  = blockIdx.x >> 7;
    const int l0 = (blockIdx.x & 127) * TOK;
    const int d  = threadIdx.x;

    __shared__ float xc_s[TOK][512];
    __shared__ float xdbl_s[TOK][48];

    {
        float4 cw = ((const float4*)conv_w)[d];
        float cb = conv_b[d];
        const float* xcol = g_xz + (size_t)(b * 2048 + l0) * 1024 + d;
        float w0 = (l0 - 3 >= 0) ? xcol[-3 * 1024] : 0.f;
        float w1 = (l0 - 2 >= 0) ? xcol[-2 * 1024] : 0.f;
        float w2 = (l0 - 1 >= 0) ? xcol[-1 * 1024] : 0.f;
#pragma unroll
        for (int t = 0; t < TOK; ++t) {
            float cur = xcol[t * 1024];
            float acc = cb;
            acc = fmaf(w0, cw.x, acc);
            acc = fmaf(w1, cw.y, acc);
            acc = fmaf(w2, cw.z, acc);
            acc = fmaf(cur, cw.w, acc);
            xc_s[t][d] = silu_f(acc);
            w0 = w1; w1 = w2; w2 = cur;
        }
    }
    __syncthreads();

    {
        const int warp = d >> 5, lane = d & 31;
        float4 wv[3][4];
        const float4* xw4 = (const float4*)x_proj_w;
#pragma unroll
        for (int jj = 0; jj < 3; ++jj) {
            const float4* wrow = xw4 + (size_t)(warp * 3 + jj) * 128;
#pragma unroll
            for (int q = 0; q < 4; ++q)
                wv[jj][q] = wrow[lane + q * 32];
        }
#pragma unroll
        for (int t = 0; t < TOK; ++t) {
            float4 xv[4];
            const float4* xr = (const float4*)&xc_s[t][0];
#pragma unroll
            for (int q = 0; q < 4; ++q) xv[q] = xr[lane + q * 32];
            float a0 = 0.f, a1 = 0.f, a2 = 0.f;
#pragma unroll
            for (int q = 0; q < 4; ++q) {
                a0 = fmaf(xv[q].x, wv[0][q].x, a0); a0 = fmaf(xv[q].y, wv[0][q].y, a0);
                a0 = fmaf(xv[q].z, wv[0][q].z, a0); a0 = fmaf(xv[q].w, wv[0][q].w, a0);
                a1 = fmaf(xv[q].x, wv[1][q].x, a1); a1 = fmaf(xv[q].y, wv[1][q].y, a1);
                a1 = fmaf(xv[q].z, wv[1][q].z, a1); a1 = fmaf(xv[q].w, wv[1][q].w, a1);
                a2 = fmaf(xv[q].x, wv[2][q].x, a2); a2 = fmaf(xv[q].y, wv[2][q].y, a2);
                a2 = fmaf(xv[q].z, wv[2][q].z, a2); a2 = fmaf(xv[q].w, wv[2][q].w, a2);
            }
#pragma unroll
            for (int off = 16; off; off >>= 1) {
                a0 += __shfl_xor_sync(0xffffffffu, a0, off);
                a1 += __shfl_xor_sync(0xffffffffu, a1, off);
                a2 += __shfl_xor_sync(0xffffffffu, a2, off);
            }
            if (lane == 0) {
                xdbl_s[t][warp * 3 + 0] = a0;
                xdbl_s[t][warp * 3 + 1] = a1;
                xdbl_s[t][warp * 3 + 2] = a2;
            }
        }
    }
    __syncthreads();

    {
        const float4* dw = (const float4*)(dt_proj_w + d * 16);
        float4 dw0 = dw[0], dw1 = dw[1], dw2 = dw[2], dw3 = dw[3];
        const float dtb = dt_proj_b[d];
        const float Dv = D_skip[d];
        const float* zptr = g_xz + (size_t)(b * 2048 + l0) * 1024 + 512 + d;
        float4* outp = g_scanin + (size_t)(b * 2048 + l0) * 512 + d;
#pragma unroll
        for (int t = 0; t < TOK; ++t) {
            const float4* xr = (const float4*)&xdbl_s[t][0];
            float4 x0 = xr[0], x1 = xr[1], x2 = xr[2], x3 = xr[3];
            float dt = dtb;
            dt = fmaf(x0.x, dw0.x, dt); dt = fmaf(x0.y, dw0.y, dt);
            dt = fmaf(x0.z, dw0.z, dt); dt = fmaf(x0.w, dw0.w, dt);
            dt = fmaf(x1.x, dw1.x, dt); dt = fmaf(x1.y, dw1.y, dt);
            dt = fmaf(x1.z, dw1.z, dt); dt = fmaf(x1.w, dw1.w, dt);
            dt = fmaf(x2.x, dw2.x, dt); dt = fmaf(x2.y, dw2.y, dt);
            dt = fmaf(x2.z, dw2.z, dt); dt = fmaf(x2.w, dw2.w, dt);
            dt = fmaf(x3.x, dw3.x, dt); dt = fmaf(x3.y, dw3.y, dt);
            dt = fmaf(x3.z, dw3.z, dt); dt = fmaf(x3.w, dw3.w, dt);
            float delta = (dt > 20.f) ? dt : __logf(1.f + __expf(dt));
            float xc = xc_s[t][d];
            float sz = zptr[(size_t)t * 1024];
            outp[(size_t)t * 512] = make_float4(delta, delta * xc, sz, xc * Dv);
        }
    }

    if (d < TOK * DSTATE) {
        const int t = d >> 4, n = d & 15;
        g_bc[(size_t)(b * 2048 + l0 + t) * 16 + n] =
            make_float2(xdbl_s[t][16 + n], xdbl_s[t][32 + n]);
    }
}

// ---------------- diagonal selective scan (v6: batched reduction) ---------
// cp.async depth-4 pipeline (proven). NEW: the 3-level shfl reduction is
// deferred and batched across the 8 steps of each stage, so the per-step
// critical path is just exp2+fma instead of exp2+fma+3 serial shfls.
#define SDEPTH 4
__global__ void __launch_bounds__(128)
scan_kernel(const float* __restrict__ A_log)
{
    __shared__ float4 sv[4][SDEPTH][8][4];
    __shared__ float4 sbc[4][SDEPTH][8][8];

    const int wid = threadIdx.x >> 5;
    const int lane = threadIdx.x & 31;
    const int w = blockIdx.x * 4 + wid;
    const int b = w >> 7;
    const int dbase = (w & 127) * 4;
    const int li = lane & 7;
    const int dsub = lane >> 3;
    const int d = dbase + dsub;
    const int n0 = li * 2;

    const float LOG2E = 1.44269504f;
    const float An0 = -__expf(A_log[d * 16 + n0])     * LOG2E;
    const float An1 = -__expf(A_log[d * 16 + n0 + 1]) * LOG2E;

    const float4* vsrc  = g_scanin + (size_t)(b * 2048) * 512;
    const float4* bcsrc = reinterpret_cast<const float4*>(g_bc)
                          + (size_t)(b * 2048) * 8;
    float* yp = g_y + (size_t)(b * 2048) * 512 + d;

    const int lv_t = lane >> 2, lv_d = lane & 3;
    const int lb_t = lane >> 3, lb_q = lane & 7;

    float h0 = 0.f, h1 = 0.f;

#pragma unroll
    for (int s = 0; s < SDEPTH - 1; ++s) {
        const int tb = s * 8;
        uint32_t dv = (uint32_t)__cvta_generic_to_shared(&sv[wid][s][lv_t][lv_d]);
        const float4* pv = vsrc + (size_t)(tb + lv_t) * 512 + (dbase + lv_d);
        asm volatile("cp.async.cg.shared.global [%0], [%1], 16;"
                     :: "r"(dv), "l"(pv) : "memory");
        uint32_t db0 = (uint32_t)__cvta_generic_to_shared(&sbc[wid][s][lb_t][lb_q]);
        const float4* pb0 = bcsrc + (size_t)(tb + lb_t) * 8 + lb_q;
        asm volatile("cp.async.cg.shared.global [%0], [%1], 16;"
                     :: "r"(db0), "l"(pb0) : "memory");
        uint32_t db1 = (uint32_t)__cvta_generic_to_shared(&sbc[wid][s][lb_t + 4][lb_q]);
        const float4* pb1 = bcsrc + (size_t)(tb + lb_t + 4) * 8 + lb_q;
        asm volatile("cp.async.cg.shared.global [%0], [%1], 16;"
                     :: "r"(db1), "l"(pb1) : "memory");
        asm volatile("cp.async.commit_group;" ::: "memory");
    }

    for (int k = 0; k < 256; ++k) {
        asm volatile("cp.async.wait_group %0;" :: "n"(SDEPTH - 2) : "memory");
        __syncwarp();
        const int cs = k & (SDEPTH - 1);

        float p[8];
#pragma unroll
        for (int j = 0; j < 8; ++j) {
            float4 v  = sv[wid][cs][j][dsub];
            float4 bc = sbc[wid][cs][j][li];
            float dA0 = exp2f(v.x * An0);
            float dA1 = exp2f(v.x * An1);
            h0 = fmaf(dA0, h0, v.y * bc.x);
            h1 = fmaf(dA1, h1, v.y * bc.z);
            p[j] = fmaf(h0, bc.y, h1 * bc.w);
        }
        // batched 3-level reduction: 8 independent chains per level pipeline
#pragma unroll
        for (int j = 0; j < 8; ++j) p[j] += __shfl_xor_sync(0xffffffffu, p[j], 1);
#pragma unroll
        for (int j = 0; j < 8; ++j) p[j] += __shfl_xor_sync(0xffffffffu, p[j], 2);
#pragma unroll
        for (int j = 0; j < 8; ++j) p[j] += __shfl_xor_sync(0xffffffffu, p[j], 4);
        if (li == 0) {
#pragma unroll
            for (int j = 0; j < 8; ++j) {
                float4 v = sv[wid][cs][j][dsub];
                yp[(size_t)(k * 8 + j) * 512] = (p[j] + v.w) * v.z;
            }
        }

        const int ks = k + SDEPTH - 1;
        if (ks < 256) {
            const int s = ks & (SDEPTH - 1);
            const int tb = ks * 8;
            uint32_t dv = (uint32_t)__cvta_generic_to_shared(&sv[wid][s][lv_t][lv_d]);
            const float4* pv = vsrc + (size_t)(tb + lv_t) * 512 + (dbase + lv_d);
            asm volatile("cp.async.cg.shared.global [%0], [%1], 16;"
                         :: "r"(dv), "l"(pv) : "memory");
            uint32_t db0 = (uint32_t)__cvta_generic_to_shared(&sbc[wid][s][lb_t][lb_q]);
            const float4* pb0 = bcsrc + (size_t)(tb + lb_t) * 8 + lb_q;
            asm volatile("cp.async.cg.shared.global [%0], [%1], 16;"
                         :: "r"(db0), "l"(pb0) : "memory");
            uint32_t db1 = (uint32_t)__cvta_generic_to_shared(&sbc[wid][s][lb_t + 4][lb_q]);
            const float4* pb1 = bcsrc + (size_t)(tb + lb_t + 4) * 8 + lb_q;
            asm volatile("cp.async.cg.shared.global [%0], [%1], 16;"
                         :: "r"(db1), "l"(pb1) : "memory");
        }
        asm volatile("cp.async.commit_group;" ::: "memory");
    }
}

// ------------------------- LayerNorm stats + apply ------------------------
__global__ void stats_kernel()
{
    int b = threadIdx.x;
    if (b >= BATCH) return;
    double s = 0.0, ss = 0.0;
    for (int bm = b * 16; bm < b * 16 + 16; ++bm)
        for (int bn = 0; bn < 2; ++bn) {
            int pid = bm * 2 + bn;
            s  += (double)g_psum[2 * pid];
            ss += (double)g_psum[2 * pid + 1];
        }
    const double nd = (double)LSEQ * NOUT;
    double mu = s / nd;
    double var = ss / nd - mu * mu;
    g_stats[b] = make_float2((float)mu, (float)rsqrt(var + 1e-5));
}

__global__ void __launch_bounds__(256)
norm_kernel(float* __restrict__ out, const float* __restrict__ lnw,
            const float* __restrict__ lnb)
{
    size_t i4 = (size_t)blockIdx.x * 256 + threadIdx.x;
    size_t base = i4 * 4;
    int row = (int)(base >> 8);
    int b = row >> 11;
    int l = row & 2047;
    int o = (int)(base & 255);
    float2 st = g_stats[b];
    float4 v = *(float4*)(out + base);
    const float4 w  = *(const float4*)(lnw + (size_t)l * 256 + o);
    const float4 bb = *(const float4*)(lnb + (size_t)l * 256 + o);
    v.x = (v.x - st.x) * st.y * w.x + bb.x;
    v.y = (v.y - st.x) * st.y * w.y + bb.y;
    v.z = (v.z - st.x) * st.y * w.z + bb.z;
    v.w = (v.w - st.x) * st.y * w.w + bb.w;
    *(float4*)(out + base) = v;
}

// ------------------------------- launch -----------------------------------
extern "C" void kernel_launch(void* const* d_in, const int* in_sizes, int n_in,
                              void* d_out, int out_size)
{
    const float* inputs    = (const float*)d_in[0];
    const float* in_proj_w = (const float*)d_in[1];
    const float* conv_w    = (const float*)d_in[2];
    const float* conv_b    = (const float*)d_in[3];
    const float* x_proj_w  = (const float*)d_in[4];
    const float* dt_proj_w = (const float*)d_in[5];
    const float* dt_proj_b = (const float*)d_in[6];
    const float* A_log     = (const float*)d_in[7];
    const float* D_skip    = (const float*)d_in[8];
    const float* out_proj_w= (const float*)d_in[9];
    const float* dim_w     = (const float*)d_in[10];
    const float* dim_b     = (const float*)d_in[11];
    const float* ln_w      = (const float*)d_in[12];
    const float* ln_b      = (const float*)d_in[13];
    float* out = (float*)d_out;

    float *xz, *y, *t1;
    cudaGetSymbolAddress((void**)&xz, g_xz);
    cudaGetSymbolAddress((void**)&y,  g_y);
    cudaGetSymbolAddress((void**)&t1, g_t1);
    uint32_t *w1h, *w1l, *w2h, *w2l, *w3h, *w3l;
    cudaGetSymbolAddress((void**)&w1h, g_w1h4);
    cudaGetSymbolAddress((void**)&w1l, g_w1l4);
    cudaGetSymbolAddress((void**)&w2h, g_w2h4);
    cudaGetSymbolAddress((void**)&w2l, g_w2l4);
    cudaGetSymbolAddress((void**)&w3h, g_w3h4);
    cudaGetSymbolAddress((void**)&w3l, g_w3l4);

    cudaFuncSetAttribute(gemm_bf16_kernel<1>,
                         cudaFuncAttributeMaxDynamicSharedMemorySize, GSM_BYTES);
    cudaFuncSetAttribute(gemm_bf16_kernel<2>,
                         cudaFuncAttributeMaxDynamicSharedMemorySize, GSM_BYTES);
    cudaFuncSetAttribute(gemm_bf16_kernel<3>,
                         cudaFuncAttributeMaxDynamicSharedMemorySize, GSM_BYTES);

    // 0) pre-split the three weight matrices into blocked fragment layout
    split_blocked_kernel<<<dim3(DMODEL / 16, 1024 / 128), 256>>>(
        in_proj_w, w1h, w1l, DMODEL);
    split_blocked_kernel<<<dim3(DINNER / 16, DMODEL / 128), 256>>>(
        out_proj_w, w2h, w2l, DINNER);
    split_blocked_kernel<<<dim3(DMODEL / 16, NOUT / 128), 256>>>(
        dim_w, w3h, w3l, DMODEL);

    // 1) xz = inputs @ in_proj_w^T  [32768 x 1024], silu on z half (bn>=4)
    gemm_bf16_kernel<3><<<dim3(1024 / 128, NROWS / 128), 256, GSM_BYTES>>>(
        inputs, w1h, w1l, xz, 1024, 256, nullptr);

    // 2) conv + silu + x_proj + dt_proj, packed scan inputs
    convproj_kernel<<<NROWS / TOK, 512>>>(conv_w, conv_b, x_proj_w,
                                          dt_proj_w, dt_proj_b, D_skip);

    // 3) selective scan (v6: batched shfl reduction)
    scan_kernel<<<512, 128>>>(A_log);

    // 4) t1 = silu(y @ out_proj_w^T)  [32768 x 256]
    gemm_bf16_kernel<1><<<dim3(256 / 128, NROWS / 128), 256, GSM_BYTES>>>(
        y, w2h, w2l, t1, 256, 512, nullptr);

    // 5) out = t1 @ dim_w^T + dim_b, + per-block partial sums
    gemm_bf16_kernel<2><<<dim3(256 / 128, NROWS / 128), 256, GSM_BYTES>>>(
        t1, w3h, w3l, out, 256, 256, dim_b);

    // 6) per-batch LayerNorm
    stats_kernel<<<1, 32>>>();
    norm_kernel<<<(NROWS * NOUT / 4) / 256, 256>>>(out, ln_w, ln_b);
}

// round 15
// speedup vs baseline: 1.5448x; 1.0464x over previous
#include <cuda_runtime.h>
#include <math.h>
#include <stdint.h>

#define BATCH   16
#define LSEQ    2048
#define DMODEL  256
#define DINNER  512
#define DSTATE  16
#define NOUT    256
#define NROWS   (BATCH*LSEQ)   /* 32768 */

// ---------------- device scratch (no allocations allowed) ----------------
__device__ float  g_xz[(size_t)NROWS * 1024];        // in_proj output (x | silu(z))
__device__ float2 g_scanin[(size_t)NROWS * DINNER];  // (delta, xc)
__device__ float2 g_bc[(size_t)NROWS * DSTATE];      // (B_n, C_n) interleaved
__device__ float  g_y[(size_t)NROWS * DINNER];       // scan output (pre out_proj)
__device__ float  g_t1[(size_t)NROWS * NOUT];        // silu(out_proj)
__device__ float  g_psum[512 * 2];                   // per-block (sum, sumsq)
__device__ float2 g_stats[BATCH];                    // (mean, rstd)

// pre-split weight matrices, blocked fragment layout (1024 u32 per 128x16 tile)
__device__ uint4 g_w1h4[1024 * DMODEL / 8];
__device__ uint4 g_w1l4[1024 * DMODEL / 8];
__device__ uint4 g_w2h4[DMODEL * DINNER / 8];
__device__ uint4 g_w2l4[DMODEL * DINNER / 8];
__device__ uint4 g_w3h4[NOUT * DMODEL / 8];
__device__ uint4 g_w3l4[NOUT * DMODEL / 8];

__device__ __forceinline__ float silu_f(float v) {
    return v / (1.f + __expf(-v));
}

// ---------------------------- bf16 helpers --------------------------------
__device__ __forceinline__ uint32_t pack_bf16x2(float hi, float lo) {
    uint32_t r;
    asm("cvt.rn.bf16x2.f32 %0, %1, %2;" : "=r"(r) : "f"(hi), "f"(lo));
    return r;
}
__device__ __forceinline__ float lo_f32(uint32_t p) {
    return __uint_as_float(p << 16);
}
__device__ __forceinline__ float hi_f32(uint32_t p) {
    return __uint_as_float(p & 0xffff0000u);
}
__device__ __forceinline__ void mma_bf16(float* c, const uint32_t* a,
                                         const uint32_t* b) {
    asm volatile(
        "mma.sync.aligned.m16n8k16.row.col.f32.bf16.bf16.f32 "
        "{%0,%1,%2,%3}, {%4,%5,%6,%7}, {%8,%9}, {%0,%1,%2,%3};"
        : "+f"(c[0]), "+f"(c[1]), "+f"(c[2]), "+f"(c[3])
        : "r"(a[0]), "r"(a[1]), "r"(a[2]), "r"(a[3]), "r"(b[0]), "r"(b[1]));
}

// -------- fp32 [M x K] -> blocked-split bf16 hi/lo (round-10 proven) -------
__global__ void __launch_bounds__(256)
split_blocked_kernel(const float* __restrict__ src, uint32_t* __restrict__ hi,
                     uint32_t* __restrict__ lo, int K)
{
    __shared__ float s[128][20];
    const int t = threadIdx.x;
    const int kt = blockIdx.x;
    const int rt = blockIdx.y;
    const float* sp = src + (size_t)rt * 128 * K + kt * 16;
#pragma unroll
    for (int i = 0; i < 2; ++i) {
        const int fi = t + i * 256;
        const int r = fi >> 2, kq = fi & 3;
        float4 v = *(const float4*)(sp + (size_t)r * K + kq * 4);
        *(float4*)&s[r][kq * 4] = v;
    }
    __syncthreads();
    const size_t tb = ((size_t)rt * gridDim.x + kt) << 10;
    const int r = t >> 1, kh = t & 1;
#pragma unroll
    for (int i = 0; i < 4; ++i) {
        const int k2 = kh * 4 + i;
        float f0 = s[r][2 * k2], f1 = s[r][2 * k2 + 1];
        uint32_t h = pack_bf16x2(f1, f0);
        uint32_t l = pack_bf16x2(f1 - hi_f32(h), f0 - lo_f32(h));
        hi[tb + i * 256 + t] = h;
        lo[tb + i * 256 + t] = l;
    }
}

// -------------------- 3x-bf16 tensor-core NT GEMM (v4) --------------------
#define KSTR 264
#define NSTAGE 4
#define RAW_F4   (NSTAGE * 512)
#define ABUFN    (4 * KSTR)
#define OFF_AH   32768
#define OFF_AL   (32768 + 2 * ABUFN * 4)
#define OFF_BS   (OFF_AL + 2 * ABUFN * 4)
#define BSTAGE_B 8448
#define GSM_BYTES (OFF_BS + NSTAGE * BSTAGE_B) /* 83456 */

template <int EPI>
__global__ void __launch_bounds__(256, 2)
gemm_bf16_kernel(const float* __restrict__ A,
                 const uint32_t* __restrict__ Bhg, const uint32_t* __restrict__ Blg,
                 float* __restrict__ C, int N, int K,
                 const float* __restrict__ bias)
{
    extern __shared__ char sm[];
    float4*   rawA = (float4*)sm;
    uint32_t* AhP  = (uint32_t*)(sm + OFF_AH);
    uint32_t* AlP  = (uint32_t*)(sm + OFF_AL);
    __shared__ float red_s[256], red_ss[256];

    const int tid = threadIdx.x;
    const int wid = tid >> 5;
    const int lane = tid & 31;
    const int grp = lane >> 2;
    const int tg  = lane & 3;
    const int warp_m = wid & 1;
    const int warp_n = wid >> 1;
    const int bm = blockIdx.y, bn = blockIdx.x;

    const int lrow = tid >> 2;
    const int lkq  = tid & 3;

    const int k2a = lkq * 2, k2b = lkq * 2 + 1;
    const int sa_row = k2a & 3, sa_kh = k2a >> 2;
    const int sb_row = k2b & 3, sb_kh = k2b >> 2;

    const int nkt = K >> 4;
    const float* Ag = A + (size_t)(bm * 128 + lrow) * K + lkq * 4;
    const size_t rstep = (size_t)64 * K;
    const int bdoff = (tid >> 6) * 1056 + (tid & 63) * 16;

    float acc[4][4][4] = {};

#define GISSUE(ktv) do {                                                     \
    const int _kt = (ktv);                                                   \
    if (_kt < nkt) {                                                         \
        const int _s = _kt & (NSTAGE - 1);                                   \
        uint32_t _da0 = (uint32_t)__cvta_generic_to_shared(&rawA[_s*512 + tid]);     \
        uint32_t _da1 = (uint32_t)__cvta_generic_to_shared(&rawA[_s*512 + 256+tid]); \
        const float* _pa = Ag + _kt * 16;                                    \
        asm volatile("cp.async.cg.shared.global [%0], [%1], 16;"             \
                     :: "r"(_da0), "l"(_pa) : "memory");                     \
        asm volatile("cp.async.cg.shared.global [%0], [%1], 16;"             \
                     :: "r"(_da1), "l"(_pa + rstep) : "memory");             \
        uint32_t _db = (uint32_t)__cvta_generic_to_shared(                   \
                           sm + OFF_BS + _s * BSTAGE_B + bdoff);             \
        const size_t _gb = (((size_t)bn * nkt + _kt) << 10) + tid * 4;       \
        asm volatile("cp.async.cg.shared.global [%0], [%1], 16;"             \
                     :: "r"(_db), "l"(Bhg + _gb) : "memory");                \
        asm volatile("cp.async.cg.shared.global [%0], [%1], 16;"             \
                     :: "r"(_db + 4224u), "l"(Blg + _gb) : "memory");        \
    }                                                                        \
    asm volatile("cp.async.commit_group;" ::: "memory");                    \
} while (0)

    GISSUE(0); GISSUE(1); GISSUE(2);

    for (int kt = 0; kt < nkt; ++kt) {
        asm volatile("cp.async.wait_group %0;" :: "n"(2) : "memory");
        const int rs = kt & (NSTAGE - 1);
        const int bufo = (kt & 1) * ABUFN;

#pragma unroll
        for (int rr = 0; rr < 2; ++rr) {
            const int r = lrow + rr * 64;
            float4 va = rawA[rs * 512 + rr * 256 + tid];
            uint32_t h01 = pack_bf16x2(va.y, va.x);
            uint32_t h23 = pack_bf16x2(va.w, va.z);
            uint32_t l01 = pack_bf16x2(va.y - hi_f32(h01), va.x - lo_f32(h01));
            uint32_t l23 = pack_bf16x2(va.w - hi_f32(h23), va.z - lo_f32(h23));
            AhP[bufo + sa_row * KSTR + r * 2 + sa_kh] = h01;
            AlP[bufo + sa_row * KSTR + r * 2 + sa_kh] = l01;
            AhP[bufo + sb_row * KSTR + r * 2 + sb_kh] = h23;
            AlP[bufo + sb_row * KSTR + r * 2 + sb_kh] = l23;
        }

        __syncthreads();
        GISSUE(kt + 3);

        const uint32_t* Th = (const uint32_t*)(sm + OFF_BS + rs * BSTAGE_B);
        const uint32_t* Tl = Th + 1056;

        uint2 af[4][2], bh[4], bl[4];
#pragma unroll
        for (int mi = 0; mi < 4; ++mi) {
            const int m = warp_m * 64 + mi * 16 + grp;
            af[mi][0] = *(const uint2*)&AhP[bufo + tg * KSTR + 2 * m];
            af[mi][1] = *(const uint2*)&AhP[bufo + tg * KSTR + 2 * (m + 8)];
        }
#pragma unroll
        for (int ni = 0; ni < 4; ++ni) {
            const int n = warp_n * 32 + ni * 8 + grp;
            bh[ni] = *(const uint2*)&Th[tg * KSTR + 2 * n];
            bl[ni] = *(const uint2*)&Tl[tg * KSTR + 2 * n];
        }
#pragma unroll
        for (int mi = 0; mi < 4; ++mi) {
            const uint32_t a[4] = {af[mi][0].x, af[mi][1].x,
                                   af[mi][0].y, af[mi][1].y};
#pragma unroll
            for (int ni = 0; ni < 4; ++ni) {
                const uint32_t b0[2] = {bh[ni].x, bh[ni].y};
                const uint32_t b1[2] = {bl[ni].x, bl[ni].y};
                mma_bf16(acc[mi][ni], a, b0);
                mma_bf16(acc[mi][ni], a, b1);
            }
        }
#pragma unroll
        for (int mi = 0; mi < 4; ++mi) {
            const int m = warp_m * 64 + mi * 16 + grp;
            af[mi][0] = *(const uint2*)&AlP[bufo + tg * KSTR + 2 * m];
            af[mi][1] = *(const uint2*)&AlP[bufo + tg * KSTR + 2 * (m + 8)];
        }
#pragma unroll
        for (int mi = 0; mi < 4; ++mi) {
            const uint32_t a[4] = {af[mi][0].x, af[mi][1].x,
                                   af[mi][0].y, af[mi][1].y};
#pragma unroll
            for (int ni = 0; ni < 4; ++ni) {
                const uint32_t b0[2] = {bh[ni].x, bh[ni].y};
                mma_bf16(acc[mi][ni], a, b0);
            }
        }
    }

    float s = 0.f, ss = 0.f;
    const bool dos = (EPI == 1) || (EPI == 3 && bn >= 4);
#pragma unroll
    for (int mi = 0; mi < 4; ++mi) {
        const int row0 = bm * 128 + warp_m * 64 + mi * 16 + grp;
#pragma unroll
        for (int ni = 0; ni < 4; ++ni) {
            const int col = bn * 128 + warp_n * 32 + ni * 8 + tg * 2;
            float v0 = acc[mi][ni][0], v1 = acc[mi][ni][1];
            float v2 = acc[mi][ni][2], v3 = acc[mi][ni][3];
            if (dos) { v0 = silu_f(v0); v1 = silu_f(v1);
                       v2 = silu_f(v2); v3 = silu_f(v3); }
            if (EPI == 2) {
                const float b0 = bias[col], b1 = bias[col + 1];
                v0 += b0; v1 += b1; v2 += b0; v3 += b1;
                s += v0 + v1 + v2 + v3;
                ss += v0 * v0 + v1 * v1 + v2 * v2 + v3 * v3;
            }
            *(float2*)(C + (size_t)row0 * N + col)       = make_float2(v0, v1);
            *(float2*)(C + (size_t)(row0 + 8) * N + col) = make_float2(v2, v3);
        }
    }

    if (EPI == 2) {
        red_s[tid] = s; red_ss[tid] = ss;
        __syncthreads();
        for (int off = 128; off > 0; off >>= 1) {
            if (tid < off) { red_s[tid] += red_s[tid + off];
                             red_ss[tid] += red_ss[tid + off]; }
            __syncthreads();
        }
        if (tid == 0) {
            int pid = bm * gridDim.x + bn;
            g_psum[2 * pid] = red_s[0];
            g_psum[2 * pid + 1] = red_ss[0];
        }
    }
}

// ---------- fused causal conv + SiLU + x_proj + dt_proj + pack -----------
// v2: stores only (delta, xc) — 8B/elem; z no longer read here.
#define TOK 16
__global__ void __launch_bounds__(512, 2)
convproj_kernel(const float* __restrict__ conv_w, const float* __restrict__ conv_b,
                const float* __restrict__ x_proj_w, const float* __restrict__ dt_proj_w,
                const float* __restrict__ dt_proj_b)
{
    const int b  = blockIdx.x >> 7;
    const int l0 = (blockIdx.x & 127) * TOK;
    const int d  = threadIdx.x;

    __shared__ float xc_s[TOK][512];
    __shared__ float xdbl_s[TOK][48];

    {
        float4 cw = ((const float4*)conv_w)[d];
        float cb = conv_b[d];
        const float* xcol = g_xz + (size_t)(b * 2048 + l0) * 1024 + d;
        float w0 = (l0 - 3 >= 0) ? xcol[-3 * 1024] : 0.f;
        float w1 = (l0 - 2 >= 0) ? xcol[-2 * 1024] : 0.f;
        float w2 = (l0 - 1 >= 0) ? xcol[-1 * 1024] : 0.f;
#pragma unroll
        for (int t = 0; t < TOK; ++t) {
            float cur = xcol[t * 1024];
            float acc = cb;
            acc = fmaf(w0, cw.x, acc);
            acc = fmaf(w1, cw.y, acc);
            acc = fmaf(w2, cw.z, acc);
            acc = fmaf(cur, cw.w, acc);
            xc_s[t][d] = silu_f(acc);
            w0 = w1; w1 = w2; w2 = cur;
        }
    }
    __syncthreads();

    {
        const int warp = d >> 5, lane = d & 31;
        float4 wv[3][4];
        const float4* xw4 = (const float4*)x_proj_w;
#pragma unroll
        for (int jj = 0; jj < 3; ++jj) {
            const float4* wrow = xw4 + (size_t)(warp * 3 + jj) * 128;
#pragma unroll
            for (int q = 0; q < 4; ++q)
                wv[jj][q] = wrow[lane + q * 32];
        }
#pragma unroll
        for (int t = 0; t < TOK; ++t) {
            float4 xv[4];
            const float4* xr = (const float4*)&xc_s[t][0];
#pragma unroll
            for (int q = 0; q < 4; ++q) xv[q] = xr[lane + q * 32];
            float a0 = 0.f, a1 = 0.f, a2 = 0.f;
#pragma unroll
            for (int q = 0; q < 4; ++q) {
                a0 = fmaf(xv[q].x, wv[0][q].x, a0); a0 = fmaf(xv[q].y, wv[0][q].y, a0);
                a0 = fmaf(xv[q].z, wv[0][q].z, a0); a0 = fmaf(xv[q].w, wv[0][q].w, a0);
                a1 = fmaf(xv[q].x, wv[1][q].x, a1); a1 = fmaf(xv[q].y, wv[1][q].y, a1);
                a1 = fmaf(xv[q].z, wv[1][q].z, a1); a1 = fmaf(xv[q].w, wv[1][q].w, a1);
                a2 = fmaf(xv[q].x, wv[2][q].x, a2); a2 = fmaf(xv[q].y, wv[2][q].y, a2);
                a2 = fmaf(xv[q].z, wv[2][q].z, a2); a2 = fmaf(xv[q].w, wv[2][q].w, a2);
            }
#pragma unroll
            for (int off = 16; off; off >>= 1) {
                a0 += __shfl_xor_sync(0xffffffffu, a0, off);
                a1 += __shfl_xor_sync(0xffffffffu, a1, off);
                a2 += __shfl_xor_sync(0xffffffffu, a2, off);
            }
            if (lane == 0) {
                xdbl_s[t][warp * 3 + 0] = a0;
                xdbl_s[t][warp * 3 + 1] = a1;
                xdbl_s[t][warp * 3 + 2] = a2;
            }
        }
    }
    __syncthreads();

    {
        const float4* dw = (const float4*)(dt_proj_w + d * 16);
        float4 dw0 = dw[0], dw1 = dw[1], dw2 = dw[2], dw3 = dw[3];
        const float dtb = dt_proj_b[d];
        float2* outp = g_scanin + (size_t)(b * 2048 + l0) * 512 + d;
#pragma unroll
        for (int t = 0; t < TOK; ++t) {
            const float4* xr = (const float4*)&xdbl_s[t][0];
            float4 x0 = xr[0], x1 = xr[1], x2 = xr[2], x3 = xr[3];
            float dt = dtb;
            dt = fmaf(x0.x, dw0.x, dt); dt = fmaf(x0.y, dw0.y, dt);
            dt = fmaf(x0.z, dw0.z, dt); dt = fmaf(x0.w, dw0.w, dt);
            dt = fmaf(x1.x, dw1.x, dt); dt = fmaf(x1.y, dw1.y, dt);
            dt = fmaf(x1.z, dw1.z, dt); dt = fmaf(x1.w, dw1.w, dt);
            dt = fmaf(x2.x, dw2.x, dt); dt = fmaf(x2.y, dw2.y, dt);
            dt = fmaf(x2.z, dw2.z, dt); dt = fmaf(x2.w, dw2.w, dt);
            dt = fmaf(x3.x, dw3.x, dt); dt = fmaf(x3.y, dw3.y, dt);
            dt = fmaf(x3.z, dw3.z, dt); dt = fmaf(x3.w, dw3.w, dt);
            float delta = (dt > 20.f) ? dt : __logf(1.f + __expf(dt));
            outp[(size_t)t * 512] = make_float2(delta, xc_s[t][d]);
        }
    }

    if (d < TOK * DSTATE) {
        const int t = d >> 4, n = d & 15;
        g_bc[(size_t)(b * 2048 + l0 + t) * 16 + n] =
            make_float2(xdbl_s[t][16 + n], xdbl_s[t][32 + n]);
    }
}

// ---------------- diagonal selective scan (v7: compact inputs) ------------
// cp.async depth-4 pipeline; scanin is (delta, xc) float2; silu(z) read from
// g_xz (already silu'd by gemm<3>); delta*xc and xc*D computed in-register
// (identical fp32 single-rounding ops -> bit-identical output).
#define SDEPTH 4
__global__ void __launch_bounds__(128)
scan_kernel(const float* __restrict__ A_log, const float* __restrict__ D_skip)
{
    __shared__ float2 sv[4][SDEPTH][8][4];
    __shared__ float  szv[4][SDEPTH][8][4];
    __shared__ float4 sbc[4][SDEPTH][8][8];

    const int wid = threadIdx.x >> 5;
    const int lane = threadIdx.x & 31;
    const int w = blockIdx.x * 4 + wid;
    const int b = w >> 7;
    const int dbase = (w & 127) * 4;
    const int li = lane & 7;
    const int dsub = lane >> 3;
    const int d = dbase + dsub;
    const int n0 = li * 2;

    const float LOG2E = 1.44269504f;
    const float An0 = -__expf(A_log[d * 16 + n0])     * LOG2E;
    const float An1 = -__expf(A_log[d * 16 + n0 + 1]) * LOG2E;
    const float Dv = D_skip[d];

    const float2* vsrc  = g_scanin + (size_t)(b * 2048) * 512;
    const float*  zsrc  = g_xz + (size_t)(b * 2048) * 1024 + 512;
    const float4* bcsrc = reinterpret_cast<const float4*>(g_bc)
                          + (size_t)(b * 2048) * 8;
    float* yp = g_y + (size_t)(b * 2048) * 512 + d;

    const int lv_t = lane >> 1, lv_p = lane & 1;   // sv: 16 lanes, 16B each
    const int lb_t = lane >> 3, lb_q = lane & 7;   // bc: 32 lanes, 2x16B

#define SCAN_ISSUE(stg, tbase) do {                                          \
    const int _s = (stg); const int _tb = (tbase);                           \
    if (lane < 16) {                                                         \
        uint32_t _dv = (uint32_t)__cvta_generic_to_shared(                   \
            &sv[wid][_s][lv_t][lv_p * 2]);                                   \
        const float2* _pv = vsrc + (size_t)(_tb + lv_t) * 512 +              \
                            (dbase + lv_p * 2);                              \
        asm volatile("cp.async.cg.shared.global [%0], [%1], 16;"             \
                     :: "r"(_dv), "l"(_pv) : "memory");                      \
    }                                                                        \
    if (lane < 8) {                                                          \
        uint32_t _dz = (uint32_t)__cvta_generic_to_shared(                   \
            &szv[wid][_s][lane][0]);                                         \
        const float* _pz = zsrc + (size_t)(_tb + lane) * 1024 + dbase;       \
        asm volatile("cp.async.cg.shared.global [%0], [%1], 16;"             \
                     :: "r"(_dz), "l"(_pz) : "memory");                      \
    }                                                                        \
    {                                                                        \
        uint32_t _db0 = (uint32_t)__cvta_generic_to_shared(                  \
            &sbc[wid][_s][lb_t][lb_q]);                                      \
        const float4* _pb0 = bcsrc + (size_t)(_tb + lb_t) * 8 + lb_q;        \
        asm volatile("cp.async.cg.shared.global [%0], [%1], 16;"             \
                     :: "r"(_db0), "l"(_pb0) : "memory");                    \
        uint32_t _db1 = (uint32_t)__cvta_generic_to_shared(                  \
            &sbc[wid][_s][lb_t + 4][lb_q]);                                  \
        const float4* _pb1 = bcsrc + (size_t)(_tb + lb_t + 4) * 8 + lb_q;    \
        asm volatile("cp.async.cg.shared.global [%0], [%1], 16;"             \
                     :: "r"(_db1), "l"(_pb1) : "memory");                    \
    }                                                                        \
    asm volatile("cp.async.commit_group;" ::: "memory");                    \
} while (0)

    float h0 = 0.f, h1 = 0.f;

#pragma unroll
    for (int s = 0; s < SDEPTH - 1; ++s)
        SCAN_ISSUE(s, s * 8);

    for (int k = 0; k < 256; ++k) {
        asm volatile("cp.async.wait_group %0;" :: "n"(SDEPTH - 2) : "memory");
        __syncwarp();
        const int cs = k & (SDEPTH - 1);

        float p[8];
#pragma unroll
        for (int j = 0; j < 8; ++j) {
            float2 v  = sv[wid][cs][j][dsub];    // (delta, xc)
            float4 bc = sbc[wid][cs][j][li];
            float dxc = v.x * v.y;               // delta*xc (same op as before)
            float dA0 = exp2f(v.x * An0);
            float dA1 = exp2f(v.x * An1);
            h0 = fmaf(dA0, h0, dxc * bc.x);
            h1 = fmaf(dA1, h1, dxc * bc.z);
            p[j] = fmaf(h0, bc.y, h1 * bc.w);
        }
#pragma unroll
        for (int j = 0; j < 8; ++j) p[j] += __shfl_xor_sync(0xffffffffu, p[j], 1);
#pragma unroll
        for (int j = 0; j < 8; ++j) p[j] += __shfl_xor_sync(0xffffffffu, p[j], 2);
#pragma unroll
        for (int j = 0; j < 8; ++j) p[j] += __shfl_xor_sync(0xffffffffu, p[j], 4);
        if (li == 0) {
#pragma unroll
            for (int j = 0; j < 8; ++j) {
                float xc = sv[wid][cs][j][dsub].y;
                float sz = szv[wid][cs][j][dsub];
                yp[(size_t)(k * 8 + j) * 512] = (p[j] + xc * Dv) * sz;
            }
        }

        const int ks = k + SDEPTH - 1;
        if (ks < 256) {
            SCAN_ISSUE(ks & (SDEPTH - 1), ks * 8);
        } else {
            asm volatile("cp.async.commit_group;" ::: "memory");
        }
    }
}

// ------------------------- LayerNorm stats + apply ------------------------
__global__ void stats_kernel()
{
    int b = threadIdx.x;
    if (b >= BATCH) return;
    double s = 0.0, ss = 0.0;
    for (int bm = b * 16; bm < b * 16 + 16; ++bm)
        for (int bn = 0; bn < 2; ++bn) {
            int pid = bm * 2 + bn;
            s  += (double)g_psum[2 * pid];
            ss += (double)g_psum[2 * pid + 1];
        }
    const double nd = (double)LSEQ * NOUT;
    double mu = s / nd;
    double var = ss / nd - mu * mu;
    g_stats[b] = make_float2((float)mu, (float)rsqrt(var + 1e-5));
}

__global__ void __launch_bounds__(256)
norm_kernel(float* __restrict__ out, const float* __restrict__ lnw,
            const float* __restrict__ lnb)
{
    size_t i4 = (size_t)blockIdx.x * 256 + threadIdx.x;
    size_t base = i4 * 4;
    int row = (int)(base >> 8);
    int b = row >> 11;
    int l = row & 2047;
    int o = (int)(base & 255);
    float2 st = g_stats[b];
    float4 v = *(float4*)(out + base);
    const float4 w  = *(const float4*)(lnw + (size_t)l * 256 + o);
    const float4 bb = *(const float4*)(lnb + (size_t)l * 256 + o);
    v.x = (v.x - st.x) * st.y * w.x + bb.x;
    v.y = (v.y - st.x) * st.y * w.y + bb.y;
    v.z = (v.z - st.x) * st.y * w.z + bb.z;
    v.w = (v.w - st.x) * st.y * w.w + bb.w;
    *(float4*)(out + base) = v;
}

// ------------------------------- launch -----------------------------------
extern "C" void kernel_launch(void* const* d_in, const int* in_sizes, int n_in,
                              void* d_out, int out_size)
{
    const float* inputs    = (const float*)d_in[0];
    const float* in_proj_w = (const float*)d_in[1];
    const float* conv_w    = (const float*)d_in[2];
    const float* conv_b    = (const float*)d_in[3];
    const float* x_proj_w  = (const float*)d_in[4];
    const float* dt_proj_w = (const float*)d_in[5];
    const float* dt_proj_b = (const float*)d_in[6];
    const float* A_log     = (const float*)d_in[7];
    const float* D_skip    = (const float*)d_in[8];
    const float* out_proj_w= (const float*)d_in[9];
    const float* dim_w     = (const float*)d_in[10];
    const float* dim_b     = (const float*)d_in[11];
    const float* ln_w      = (const float*)d_in[12];
    const float* ln_b      = (const float*)d_in[13];
    float* out = (float*)d_out;

    float *xz, *y, *t1;
    cudaGetSymbolAddress((void**)&xz, g_xz);
    cudaGetSymbolAddress((void**)&y,  g_y);
    cudaGetSymbolAddress((void**)&t1, g_t1);
    uint32_t *w1h, *w1l, *w2h, *w2l, *w3h, *w3l;
    cudaGetSymbolAddress((void**)&w1h, g_w1h4);
    cudaGetSymbolAddress((void**)&w1l, g_w1l4);
    cudaGetSymbolAddress((void**)&w2h, g_w2h4);
    cudaGetSymbolAddress((void**)&w2l, g_w2l4);
    cudaGetSymbolAddress((void**)&w3h, g_w3h4);
    cudaGetSymbolAddress((void**)&w3l, g_w3l4);

    cudaFuncSetAttribute(gemm_bf16_kernel<1>,
                         cudaFuncAttributeMaxDynamicSharedMemorySize, GSM_BYTES);
    cudaFuncSetAttribute(gemm_bf16_kernel<2>,
                         cudaFuncAttributeMaxDynamicSharedMemorySize, GSM_BYTES);
    cudaFuncSetAttribute(gemm_bf16_kernel<3>,
                         cudaFuncAttributeMaxDynamicSharedMemorySize, GSM_BYTES);

    // 0) pre-split the three weight matrices into blocked fragment layout
    split_blocked_kernel<<<dim3(DMODEL / 16, 1024 / 128), 256>>>(
        in_proj_w, w1h, w1l, DMODEL);
    split_blocked_kernel<<<dim3(DINNER / 16, DMODEL / 128), 256>>>(
        out_proj_w, w2h, w2l, DINNER);
    split_blocked_kernel<<<dim3(DMODEL / 16, NOUT / 128), 256>>>(
        dim_w, w3h, w3l, DMODEL);

    // 1) xz = inputs @ in_proj_w^T  [32768 x 1024], silu on z half (bn>=4)
    gemm_bf16_kernel<3><<<dim3(1024 / 128, NROWS / 128), 256, GSM_BYTES>>>(
        inputs, w1h, w1l, xz, 1024, 256, nullptr);

    // 2) conv + silu + x_proj + dt_proj, compact (delta, xc) pack
    convproj_kernel<<<NROWS / TOK, 512>>>(conv_w, conv_b, x_proj_w,
                                          dt_proj_w, dt_proj_b);

    // 3) selective scan (v7: compact inputs, z from g_xz)
    scan_kernel<<<512, 128>>>(A_log, D_skip);

    // 4) t1 = silu(y @ out_proj_w^T)  [32768 x 256]
    gemm_bf16_kernel<1><<<dim3(256 / 128, NROWS / 128), 256, GSM_BYTES>>>(
        y, w2h, w2l, t1, 256, 512, nullptr);

    // 5) out = t1 @ dim_w^T + dim_b, + per-block partial sums
    gemm_bf16_kernel<2><<<dim3(256 / 128, NROWS / 128), 256, GSM_BYTES>>>(
        t1, w3h, w3l, out, 256, 256, dim_b);

    // 6) per-batch LayerNorm
    stats_kernel<<<1, 32>>>();
    norm_kernel<<<(NROWS * NOUT / 4) / 256, 256>>>(out, ln_w, ln_b);
}

// round 16
// speedup vs baseline: 1.6106x; 1.0426x over previous
#include <cuda_runtime.h>
#include <math.h>
#include <stdint.h>

#define BATCH   16
#define LSEQ    2048
#define DMODEL  256
#define DINNER  512
#define DSTATE  16
#define NOUT    256
#define NROWS   (BATCH*LSEQ)   /* 32768 */

// ---------------- device scratch (no allocations allowed) ----------------
__device__ float  g_xz[(size_t)NROWS * 1024];        // in_proj output (x | silu(z))
__device__ float2 g_scanin[(size_t)NROWS * DINNER];  // (delta, xc)
__device__ float2 g_bc[(size_t)NROWS * DSTATE];      // (B_n, C_n) interleaved
__device__ float  g_y[(size_t)NROWS * DINNER];       // scan output (pre out_proj)
__device__ float  g_t1[(size_t)NROWS * NOUT];        // silu(out_proj)
__device__ float  g_psum[512 * 2];                   // per-block (sum, sumsq)
__device__ float2 g_stats[BATCH];                    // (mean, rstd)

// pre-split weight matrices, blocked fragment layout (1024 u32 per 128x16 tile)
__device__ uint4 g_w1h4[1024 * DMODEL / 8];
__device__ uint4 g_w1l4[1024 * DMODEL / 8];
__device__ uint4 g_w2h4[DMODEL * DINNER / 8];
__device__ uint4 g_w2l4[DMODEL * DINNER / 8];
__device__ uint4 g_w3h4[NOUT * DMODEL / 8];
__device__ uint4 g_w3l4[NOUT * DMODEL / 8];

// x_proj_w pre-split in per-(kstep, ntile, lane) fragment order
__device__ uint32_t g_wxh[32 * 6 * 64];   // 12288 u32
__device__ uint32_t g_wxl[32 * 6 * 64];

__device__ __forceinline__ float silu_f(float v) {
    return v / (1.f + __expf(-v));
}

// ---------------------------- bf16 helpers --------------------------------
__device__ __forceinline__ uint32_t pack_bf16x2(float hi, float lo) {
    uint32_t r;
    asm("cvt.rn.bf16x2.f32 %0, %1, %2;" : "=r"(r) : "f"(hi), "f"(lo));
    return r;
}
__device__ __forceinline__ float lo_f32(uint32_t p) {
    return __uint_as_float(p << 16);
}
__device__ __forceinline__ float hi_f32(uint32_t p) {
    return __uint_as_float(p & 0xffff0000u);
}
__device__ __forceinline__ void mma_bf16(float* c, const uint32_t* a,
                                         const uint32_t* b) {
    asm volatile(
        "mma.sync.aligned.m16n8k16.row.col.f32.bf16.bf16.f32 "
        "{%0,%1,%2,%3}, {%4,%5,%6,%7}, {%8,%9}, {%0,%1,%2,%3};"
        : "+f"(c[0]), "+f"(c[1]), "+f"(c[2]), "+f"(c[3])
        : "r"(a[0]), "r"(a[1]), "r"(a[2]), "r"(a[3]), "r"(b[0]), "r"(b[1]));
}

// -------- fp32 [M x K] -> blocked-split bf16 hi/lo (round-10 proven) -------
__global__ void __launch_bounds__(256)
split_blocked_kernel(const float* __restrict__ src, uint32_t* __restrict__ hi,
                     uint32_t* __restrict__ lo, int K)
{
    __shared__ float s[128][20];
    const int t = threadIdx.x;
    const int kt = blockIdx.x;
    const int rt = blockIdx.y;
    const float* sp = src + (size_t)rt * 128 * K + kt * 16;
#pragma unroll
    for (int i = 0; i < 2; ++i) {
        const int fi = t + i * 256;
        const int r = fi >> 2, kq = fi & 3;
        float4 v = *(const float4*)(sp + (size_t)r * K + kq * 4);
        *(float4*)&s[r][kq * 4] = v;
    }
    __syncthreads();
    const size_t tb = ((size_t)rt * gridDim.x + kt) << 10;
    const int r = t >> 1, kh = t & 1;
#pragma unroll
    for (int i = 0; i < 4; ++i) {
        const int k2 = kh * 4 + i;
        float f0 = s[r][2 * k2], f1 = s[r][2 * k2 + 1];
        uint32_t h = pack_bf16x2(f1, f0);
        uint32_t l = pack_bf16x2(f1 - hi_f32(h), f0 - lo_f32(h));
        hi[tb + i * 256 + t] = h;
        lo[tb + i * 256 + t] = l;
    }
}

// -------- x_proj_w [48 x 512] -> B-fragment split layout --------------------
__global__ void __launch_bounds__(192)
wxsplit_kernel(const float* __restrict__ xw)
{
    const int ks = blockIdx.x;            // 0..31
    const int nt = threadIdx.x >> 5;      // 0..5
    const int lane = threadIdx.x & 31;
    const int n = nt * 8 + (lane >> 2);
    const int k0 = ks * 16 + (lane & 3) * 2;
    const float* wr = xw + n * 512;
    float w0 = wr[k0], w1 = wr[k0 + 1], w8 = wr[k0 + 8], w9 = wr[k0 + 9];
    uint32_t b0h = pack_bf16x2(w1, w0);
    uint32_t b1h = pack_bf16x2(w9, w8);
    uint32_t b0l = pack_bf16x2(w1 - hi_f32(b0h), w0 - lo_f32(b0h));
    uint32_t b1l = pack_bf16x2(w9 - hi_f32(b1h), w8 - lo_f32(b1h));
    const int idx = (ks * 6 + nt) * 32 + lane;
    ((uint2*)g_wxh)[idx] = make_uint2(b0h, b1h);
    ((uint2*)g_wxl)[idx] = make_uint2(b0l, b1l);
}

// -------------------- 3x-bf16 tensor-core NT GEMM (v4) --------------------
#define KSTR 264
#define NSTAGE 4
#define RAW_F4   (NSTAGE * 512)
#define ABUFN    (4 * KSTR)
#define OFF_AH   32768
#define OFF_AL   (32768 + 2 * ABUFN * 4)
#define OFF_BS   (OFF_AL + 2 * ABUFN * 4)
#define BSTAGE_B 8448
#define GSM_BYTES (OFF_BS + NSTAGE * BSTAGE_B) /* 83456 */

template <int EPI>
__global__ void __launch_bounds__(256, 2)
gemm_bf16_kernel(const float* __restrict__ A,
                 const uint32_t* __restrict__ Bhg, const uint32_t* __restrict__ Blg,
                 float* __restrict__ C, int N, int K,
                 const float* __restrict__ bias)
{
    extern __shared__ char sm[];
    float4*   rawA = (float4*)sm;
    uint32_t* AhP  = (uint32_t*)(sm + OFF_AH);
    uint32_t* AlP  = (uint32_t*)(sm + OFF_AL);
    __shared__ float red_s[256], red_ss[256];

    const int tid = threadIdx.x;
    const int wid = tid >> 5;
    const int lane = tid & 31;
    const int grp = lane >> 2;
    const int tg  = lane & 3;
    const int warp_m = wid & 1;
    const int warp_n = wid >> 1;
    const int bm = blockIdx.y, bn = blockIdx.x;

    const int lrow = tid >> 2;
    const int lkq  = tid & 3;

    const int k2a = lkq * 2, k2b = lkq * 2 + 1;
    const int sa_row = k2a & 3, sa_kh = k2a >> 2;
    const int sb_row = k2b & 3, sb_kh = k2b >> 2;

    const int nkt = K >> 4;
    const float* Ag = A + (size_t)(bm * 128 + lrow) * K + lkq * 4;
    const size_t rstep = (size_t)64 * K;
    const int bdoff = (tid >> 6) * 1056 + (tid & 63) * 16;

    float acc[4][4][4] = {};

#define GISSUE(ktv) do {                                                     \
    const int _kt = (ktv);                                                   \
    if (_kt < nkt) {                                                         \
        const int _s = _kt & (NSTAGE - 1);                                   \
        uint32_t _da0 = (uint32_t)__cvta_generic_to_shared(&rawA[_s*512 + tid]);     \
        uint32_t _da1 = (uint32_t)__cvta_generic_to_shared(&rawA[_s*512 + 256+tid]); \
        const float* _pa = Ag + _kt * 16;                                    \
        asm volatile("cp.async.cg.shared.global [%0], [%1], 16;"             \
                     :: "r"(_da0), "l"(_pa) : "memory");                     \
        asm volatile("cp.async.cg.shared.global [%0], [%1], 16;"             \
                     :: "r"(_da1), "l"(_pa + rstep) : "memory");             \
        uint32_t _db = (uint32_t)__cvta_generic_to_shared(                   \
                           sm + OFF_BS + _s * BSTAGE_B + bdoff);             \
        const size_t _gb = (((size_t)bn * nkt + _kt) << 10) + tid * 4;       \
        asm volatile("cp.async.cg.shared.global [%0], [%1], 16;"             \
                     :: "r"(_db), "l"(Bhg + _gb) : "memory");                \
        asm volatile("cp.async.cg.shared.global [%0], [%1], 16;"             \
                     :: "r"(_db + 4224u), "l"(Blg + _gb) : "memory");        \
    }                                                                        \
    asm volatile("cp.async.commit_group;" ::: "memory");                    \
} while (0)

    GISSUE(0); GISSUE(1); GISSUE(2);

    for (int kt = 0; kt < nkt; ++kt) {
        asm volatile("cp.async.wait_group %0;" :: "n"(2) : "memory");
        const int rs = kt & (NSTAGE - 1);
        const int bufo = (kt & 1) * ABUFN;

#pragma unroll
        for (int rr = 0; rr < 2; ++rr) {
            const int r = lrow + rr * 64;
            float4 va = rawA[rs * 512 + rr * 256 + tid];
            uint32_t h01 = pack_bf16x2(va.y, va.x);
            uint32_t h23 = pack_bf16x2(va.w, va.z);
            uint32_t l01 = pack_bf16x2(va.y - hi_f32(h01), va.x - lo_f32(h01));
            uint32_t l23 = pack_bf16x2(va.w - hi_f32(h23), va.z - lo_f32(h23));
            AhP[bufo + sa_row * KSTR + r * 2 + sa_kh] = h01;
            AlP[bufo + sa_row * KSTR + r * 2 + sa_kh] = l01;
            AhP[bufo + sb_row * KSTR + r * 2 + sb_kh] = h23;
            AlP[bufo + sb_row * KSTR + r * 2 + sb_kh] = l23;
        }

        __syncthreads();
        GISSUE(kt + 3);

        const uint32_t* Th = (const uint32_t*)(sm + OFF_BS + rs * BSTAGE_B);
        const uint32_t* Tl = Th + 1056;

        uint2 af[4][2], bh[4], bl[4];
#pragma unroll
        for (int mi = 0; mi < 4; ++mi) {
            const int m = warp_m * 64 + mi * 16 + grp;
            af[mi][0] = *(const uint2*)&AhP[bufo + tg * KSTR + 2 * m];
            af[mi][1] = *(const uint2*)&AhP[bufo + tg * KSTR + 2 * (m + 8)];
        }
#pragma unroll
        for (int ni = 0; ni < 4; ++ni) {
            const int n = warp_n * 32 + ni * 8 + grp;
            bh[ni] = *(const uint2*)&Th[tg * KSTR + 2 * n];
            bl[ni] = *(const uint2*)&Tl[tg * KSTR + 2 * n];
        }
#pragma unroll
        for (int mi = 0; mi < 4; ++mi) {
            const uint32_t a[4] = {af[mi][0].x, af[mi][1].x,
                                   af[mi][0].y, af[mi][1].y};
#pragma unroll
            for (int ni = 0; ni < 4; ++ni) {
                const uint32_t b0[2] = {bh[ni].x, bh[ni].y};
                const uint32_t b1[2] = {bl[ni].x, bl[ni].y};
                mma_bf16(acc[mi][ni], a, b0);
                mma_bf16(acc[mi][ni], a, b1);
            }
        }
#pragma unroll
        for (int mi = 0; mi < 4; ++mi) {
            const int m = warp_m * 64 + mi * 16 + grp;
            af[mi][0] = *(const uint2*)&AlP[bufo + tg * KSTR + 2 * m];
            af[mi][1] = *(const uint2*)&AlP[bufo + tg * KSTR + 2 * (m + 8)];
        }
#pragma unroll
        for (int mi = 0; mi < 4; ++mi) {
            const uint32_t a[4] = {af[mi][0].x, af[mi][1].x,
                                   af[mi][0].y, af[mi][1].y};
#pragma unroll
            for (int ni = 0; ni < 4; ++ni) {
                const uint32_t b0[2] = {bh[ni].x, bh[ni].y};
                mma_bf16(acc[mi][ni], a, b0);
            }
        }
    }

    float s = 0.f, ss = 0.f;
    const bool dos = (EPI == 1) || (EPI == 3 && bn >= 4);
#pragma unroll
    for (int mi = 0; mi < 4; ++mi) {
        const int row0 = bm * 128 + warp_m * 64 + mi * 16 + grp;
#pragma unroll
        for (int ni = 0; ni < 4; ++ni) {
            const int col = bn * 128 + warp_n * 32 + ni * 8 + tg * 2;
            float v0 = acc[mi][ni][0], v1 = acc[mi][ni][1];
            float v2 = acc[mi][ni][2], v3 = acc[mi][ni][3];
            if (dos) { v0 = silu_f(v0); v1 = silu_f(v1);
                       v2 = silu_f(v2); v3 = silu_f(v3); }
            if (EPI == 2) {
                const float b0 = bias[col], b1 = bias[col + 1];
                v0 += b0; v1 += b1; v2 += b0; v3 += b1;
                s += v0 + v1 + v2 + v3;
                ss += v0 * v0 + v1 * v1 + v2 * v2 + v3 * v3;
            }
            *(float2*)(C + (size_t)row0 * N + col)       = make_float2(v0, v1);
            *(float2*)(C + (size_t)(row0 + 8) * N + col) = make_float2(v2, v3);
        }
    }

    if (EPI == 2) {
        red_s[tid] = s; red_ss[tid] = ss;
        __syncthreads();
        for (int off = 128; off > 0; off >>= 1) {
            if (tid < off) { red_s[tid] += red_s[tid + off];
                             red_ss[tid] += red_ss[tid + off]; }
            __syncthreads();
        }
        if (tid == 0) {
            int pid = bm * gridDim.x + bn;
            g_psum[2 * pid] = red_s[0];
            g_psum[2 * pid + 1] = red_ss[0];
        }
    }
}

// ---------- fused causal conv + SiLU + x_proj(MMA) + dt_proj + pack -------
// v3: stage-2 x_proj done with split-bf16 mma.sync; K split over 16 warps,
// cross-warp reduce in smem. Dynamic smem: xc[16][520] | red[16][808] | xdbl.
#define TOK 16
#define CPSM_RED   (16 * 520 * 4)
#define CPSM_XDBL  (CPSM_RED + 16 * 808 * 4)
#define CPSM_TOTAL (CPSM_XDBL + 16 * 48 * 4)   /* 88064 */

__global__ void __launch_bounds__(512, 2)
convproj_kernel(const float* __restrict__ conv_w, const float* __restrict__ conv_b,
                const float* __restrict__ dt_proj_w, const float* __restrict__ dt_proj_b)
{
    extern __shared__ char cpsm[];
    float* xc_s   = (float*)cpsm;                   // [16][520]
    float* red    = (float*)(cpsm + CPSM_RED);      // [16][808]
    float* xdbl_s = (float*)(cpsm + CPSM_XDBL);     // [16][48]

    const int b  = blockIdx.x >> 7;
    const int l0 = (blockIdx.x & 127) * TOK;
    const int d  = threadIdx.x;
    const int wp = d >> 5, lane = d & 31;

    // ---- stage 1: causal conv + silu -> xc_s ----
    {
        float4 cw = ((const float4*)conv_w)[d];
        float cb = conv_b[d];
        const float* xcol = g_xz + (size_t)(b * 2048 + l0) * 1024 + d;
        float w0 = (l0 - 3 >= 0) ? xcol[-3 * 1024] : 0.f;
        float w1 = (l0 - 2 >= 0) ? xcol[-2 * 1024] : 0.f;
        float w2 = (l0 - 1 >= 0) ? xcol[-1 * 1024] : 0.f;
#pragma unroll
        for (int t = 0; t < TOK; ++t) {
            float cur = xcol[t * 1024];
            float acc = cb;
            acc = fmaf(w0, cw.x, acc);
            acc = fmaf(w1, cw.y, acc);
            acc = fmaf(w2, cw.z, acc);
            acc = fmaf(cur, cw.w, acc);
            xc_s[t * 520 + d] = silu_f(acc);
            w0 = w1; w1 = w2; w2 = cur;
        }
    }
    __syncthreads();

    // ---- stage 2: x_dbl = xc @ x_proj_w^T via split-bf16 mma ----
    {
        const int r  = lane >> 2;            // 0..7 (token rows r, r+8)
        const int kq = (lane & 3) * 2;
        float facc[6][4] = {};
#pragma unroll
        for (int s2 = 0; s2 < 2; ++s2) {
            const int ks = wp * 2 + s2;
            const int k0 = ks * 16 + kq;
            float2 f00 = *(const float2*)&xc_s[r * 520 + k0];
            float2 f01 = *(const float2*)&xc_s[(r + 8) * 520 + k0];
            float2 f10 = *(const float2*)&xc_s[r * 520 + k0 + 8];
            float2 f11 = *(const float2*)&xc_s[(r + 8) * 520 + k0 + 8];
            uint32_t ah[4], al[4];
            ah[0] = pack_bf16x2(f00.y, f00.x);
            ah[1] = pack_bf16x2(f01.y, f01.x);
            ah[2] = pack_bf16x2(f10.y, f10.x);
            ah[3] = pack_bf16x2(f11.y, f11.x);
            al[0] = pack_bf16x2(f00.y - hi_f32(ah[0]), f00.x - lo_f32(ah[0]));
            al[1] = pack_bf16x2(f01.y - hi_f32(ah[1]), f01.x - lo_f32(ah[1]));
            al[2] = pack_bf16x2(f10.y - hi_f32(ah[2]), f10.x - lo_f32(ah[2]));
            al[3] = pack_bf16x2(f11.y - hi_f32(ah[3]), f11.x - lo_f32(ah[3]));
#pragma unroll
            for (int nt = 0; nt < 6; ++nt) {
                uint2 bhv = ((const uint2*)g_wxh)[(ks * 6 + nt) * 32 + lane];
                uint2 blv = ((const uint2*)g_wxl)[(ks * 6 + nt) * 32 + lane];
                const uint32_t b0[2] = {bhv.x, bhv.y};
                const uint32_t b1[2] = {blv.x, blv.y};
                mma_bf16(facc[nt], ah, b0);
                mma_bf16(facc[nt], ah, b1);
                mma_bf16(facc[nt], al, b0);
            }
        }
        float* rw = red + wp * 808;
        const int n0 = (lane & 3) * 2;
#pragma unroll
        for (int nt = 0; nt < 6; ++nt) {
            const int n = nt * 8 + n0;
            *(float2*)&rw[r * 50 + n]       = make_float2(facc[nt][0], facc[nt][1]);
            *(float2*)&rw[(r + 8) * 50 + n] = make_float2(facc[nt][2], facc[nt][3]);
        }
    }
    __syncthreads();

    // ---- reduce 16 warp-partials -> xdbl_s ----
    for (int i = d; i < TOK * 48; i += 512) {
        const int t = i / 48, n = i - t * 48;
        float s = 0.f;
#pragma unroll
        for (int w2 = 0; w2 < 16; ++w2)
            s += red[w2 * 808 + t * 50 + n];
        xdbl_s[t * 48 + n] = s;
    }
    __syncthreads();

    // ---- stage 3: dt_proj + softplus + compact pack ----
    {
        const float4* dw = (const float4*)(dt_proj_w + d * 16);
        float4 dw0 = dw[0], dw1 = dw[1], dw2 = dw[2], dw3 = dw[3];
        const float dtb = dt_proj_b[d];
        float2* outp = g_scanin + (size_t)(b * 2048 + l0) * 512 + d;
#pragma unroll
        for (int t = 0; t < TOK; ++t) {
            const float4* xr = (const float4*)&xdbl_s[t * 48];
            float4 x0 = xr[0], x1 = xr[1], x2 = xr[2], x3 = xr[3];
            float dt = dtb;
            dt = fmaf(x0.x, dw0.x, dt); dt = fmaf(x0.y, dw0.y, dt);
            dt = fmaf(x0.z, dw0.z, dt); dt = fmaf(x0.w, dw0.w, dt);
            dt = fmaf(x1.x, dw1.x, dt); dt = fmaf(x1.y, dw1.y, dt);
            dt = fmaf(x1.z, dw1.z, dt); dt = fmaf(x1.w, dw1.w, dt);
            dt = fmaf(x2.x, dw2.x, dt); dt = fmaf(x2.y, dw2.y, dt);
            dt = fmaf(x2.z, dw2.z, dt); dt = fmaf(x2.w, dw2.w, dt);
            dt = fmaf(x3.x, dw3.x, dt); dt = fmaf(x3.y, dw3.y, dt);
            dt = fmaf(x3.z, dw3.z, dt); dt = fmaf(x3.w, dw3.w, dt);
            float delta = (dt > 20.f) ? dt : __logf(1.f + __expf(dt));
            outp[(size_t)t * 512] = make_float2(delta, xc_s[t * 520 + d]);
        }
    }

    if (d < TOK * DSTATE) {
        const int t = d >> 4, n = d & 15;
        g_bc[(size_t)(b * 2048 + l0 + t) * 16 + n] =
            make_float2(xdbl_s[t * 48 + 16 + n], xdbl_s[t * 48 + 32 + n]);
    }
}

// ---------------- diagonal selective scan (v7: compact inputs) ------------
#define SDEPTH 4
__global__ void __launch_bounds__(128)
scan_kernel(const float* __restrict__ A_log, const float* __restrict__ D_skip)
{
    __shared__ float2 sv[4][SDEPTH][8][4];
    __shared__ float  szv[4][SDEPTH][8][4];
    __shared__ float4 sbc[4][SDEPTH][8][8];

    const int wid = threadIdx.x >> 5;
    const int lane = threadIdx.x & 31;
    const int w = blockIdx.x * 4 + wid;
    const int b = w >> 7;
    const int dbase = (w & 127) * 4;
    const int li = lane & 7;
    const int dsub = lane >> 3;
    const int d = dbase + dsub;
    const int n0 = li * 2;

    const float LOG2E = 1.44269504f;
    const float An0 = -__expf(A_log[d * 16 + n0])     * LOG2E;
    const float An1 = -__expf(A_log[d * 16 + n0 + 1]) * LOG2E;
    const float Dv = D_skip[d];

    const float2* vsrc  = g_scanin + (size_t)(b * 2048) * 512;
    const float*  zsrc  = g_xz + (size_t)(b * 2048) * 1024 + 512;
    const float4* bcsrc = reinterpret_cast<const float4*>(g_bc)
                          + (size_t)(b * 2048) * 8;
    float* yp = g_y + (size_t)(b * 2048) * 512 + d;

    const int lv_t = lane >> 1, lv_p = lane & 1;
    const int lb_t = lane >> 3, lb_q = lane & 7;

#define SCAN_ISSUE(stg, tbase) do {                                          \
    const int _s = (stg); const int _tb = (tbase);                           \
    if (lane < 16) {                                                         \
        uint32_t _dv = (uint32_t)__cvta_generic_to_shared(                   \
            &sv[wid][_s][lv_t][lv_p * 2]);                                   \
        const float2* _pv = vsrc + (size_t)(_tb + lv_t) * 512 +              \
                            (dbase + lv_p * 2);                              \
        asm volatile("cp.async.cg.shared.global [%0], [%1], 16;"             \
                     :: "r"(_dv), "l"(_pv) : "memory");                      \
    }                                                                        \
    if (lane < 8) {                                                          \
        uint32_t _dz = (uint32_t)__cvta_generic_to_shared(                   \
            &szv[wid][_s][lane][0]);                                         \
        const float* _pz = zsrc + (size_t)(_tb + lane) * 1024 + dbase;       \
        asm volatile("cp.async.cg.shared.global [%0], [%1], 16;"             \
                     :: "r"(_dz), "l"(_pz) : "memory");                      \
    }                                                                        \
    {                                                                        \
        uint32_t _db0 = (uint32_t)__cvta_generic_to_shared(                  \
            &sbc[wid][_s][lb_t][lb_q]);                                      \
        const float4* _pb0 = bcsrc + (size_t)(_tb + lb_t) * 8 + lb_q;        \
        asm volatile("cp.async.cg.shared.global [%0], [%1], 16;"             \
                     :: "r"(_db0), "l"(_pb0) : "memory");                    \
        uint32_t _db1 = (uint32_t)__cvta_generic_to_shared(                  \
            &sbc[wid][_s][lb_t + 4][lb_q]);                                  \
        const float4* _pb1 = bcsrc + (size_t)(_tb + lb_t + 4) * 8 + lb_q;    \
        asm volatile("cp.async.cg.shared.global [%0], [%1], 16;"             \
                     :: "r"(_db1), "l"(_pb1) : "memory");                    \
    }                                                                        \
    asm volatile("cp.async.commit_group;" ::: "memory");                    \
} while (0)

    float h0 = 0.f, h1 = 0.f;

#pragma unroll
    for (int s = 0; s < SDEPTH - 1; ++s)
        SCAN_ISSUE(s, s * 8);

    for (int k = 0; k < 256; ++k) {
        asm volatile("cp.async.wait_group %0;" :: "n"(SDEPTH - 2) : "memory");
        __syncwarp();
        const int cs = k & (SDEPTH - 1);

        float p[8];
#pragma unroll
        for (int j = 0; j < 8; ++j) {
            float2 v  = sv[wid][cs][j][dsub];
            float4 bc = sbc[wid][cs][j][li];
            float dxc = v.x * v.y;
            float dA0 = exp2f(v.x * An0);
            float dA1 = exp2f(v.x * An1);
            h0 = fmaf(dA0, h0, dxc * bc.x);
            h1 = fmaf(dA1, h1, dxc * bc.z);
            p[j] = fmaf(h0, bc.y, h1 * bc.w);
        }
#pragma unroll
        for (int j = 0; j < 8; ++j) p[j] += __shfl_xor_sync(0xffffffffu, p[j], 1);
#pragma unroll
        for (int j = 0; j < 8; ++j) p[j] += __shfl_xor_sync(0xffffffffu, p[j], 2);
#pragma unroll
        for (int j = 0; j < 8; ++j) p[j] += __shfl_xor_sync(0xffffffffu, p[j], 4);
        if (li == 0) {
#pragma unroll
            for (int j = 0; j < 8; ++j) {
                float xc = sv[wid][cs][j][dsub].y;
                float sz = szv[wid][cs][j][dsub];
                yp[(size_t)(k * 8 + j) * 512] = (p[j] + xc * Dv) * sz;
            }
        }

        const int ks = k + SDEPTH - 1;
        if (ks < 256) {
            SCAN_ISSUE(ks & (SDEPTH - 1), ks * 8);
        } else {
            asm volatile("cp.async.commit_group;" ::: "memory");
        }
    }
}

// ------------------------- LayerNorm stats + apply ------------------------
__global__ void stats_kernel()
{
    int b = threadIdx.x;
    if (b >= BATCH) return;
    double s = 0.0, ss = 0.0;
    for (int bm = b * 16; bm < b * 16 + 16; ++bm)
        for (int bn = 0; bn < 2; ++bn) {
            int pid = bm * 2 + bn;
            s  += (double)g_psum[2 * pid];
            ss += (double)g_psum[2 * pid + 1];
        }
    const double nd = (double)LSEQ * NOUT;
    double mu = s / nd;
    double var = ss / nd - mu * mu;
    g_stats[b] = make_float2((float)mu, (float)rsqrt(var + 1e-5));
}

__global__ void __launch_bounds__(256)
norm_kernel(float* __restrict__ out, const float* __restrict__ lnw,
            const float* __restrict__ lnb)
{
    size_t i4 = (size_t)blockIdx.x * 256 + threadIdx.x;
    size_t base = i4 * 4;
    int row = (int)(base >> 8);
    int b = row >> 11;
    int l = row & 2047;
    int o = (int)(base & 255);
    float2 st = g_stats[b];
    float4 v = *(float4*)(out + base);
    const float4 w  = *(const float4*)(lnw + (size_t)l * 256 + o);
    const float4 bb = *(const float4*)(lnb + (size_t)l * 256 + o);
    v.x = (v.x - st.x) * st.y * w.x + bb.x;
    v.y = (v.y - st.x) * st.y * w.y + bb.y;
    v.z = (v.z - st.x) * st.y * w.z + bb.z;
    v.w = (v.w - st.x) * st.y * w.w + bb.w;
    *(float4*)(out + base) = v;
}

// ------------------------------- launch -----------------------------------
extern "C" void kernel_launch(void* const* d_in, const int* in_sizes, int n_in,
                              void* d_out, int out_size)
{
    const float* inputs    = (const float*)d_in[0];
    const float* in_proj_w = (const float*)d_in[1];
    const float* conv_w    = (const float*)d_in[2];
    const float* conv_b    = (const float*)d_in[3];
    const float* x_proj_w  = (const float*)d_in[4];
    const float* dt_proj_w = (const float*)d_in[5];
    const float* dt_proj_b = (const float*)d_in[6];
    const float* A_log     = (const float*)d_in[7];
    const float* D_skip    = (const float*)d_in[8];
    const float* out_proj_w= (const float*)d_in[9];
    const float* dim_w     = (const float*)d_in[10];
    const float* dim_b     = (const float*)d_in[11];
    const float* ln_w      = (const float*)d_in[12];
    const float* ln_b      = (const float*)d_in[13];
    float* out = (float*)d_out;

    float *xz, *y, *t1;
    cudaGetSymbolAddress((void**)&xz, g_xz);
    cudaGetSymbolAddress((void**)&y,  g_y);
    cudaGetSymbolAddress((void**)&t1, g_t1);
    uint32_t *w1h, *w1l, *w2h, *w2l, *w3h, *w3l;
    cudaGetSymbolAddress((void**)&w1h, g_w1h4);
    cudaGetSymbolAddress((void**)&w1l, g_w1l4);
    cudaGetSymbolAddress((void**)&w2h, g_w2h4);
    cudaGetSymbolAddress((void**)&w2l, g_w2l4);
    cudaGetSymbolAddress((void**)&w3h, g_w3h4);
    cudaGetSymbolAddress((void**)&w3l, g_w3l4);

    cudaFuncSetAttribute(gemm_bf16_kernel<1>,
                         cudaFuncAttributeMaxDynamicSharedMemorySize, GSM_BYTES);
    cudaFuncSetAttribute(gemm_bf16_kernel<2>,
                         cudaFuncAttributeMaxDynamicSharedMemorySize, GSM_BYTES);
    cudaFuncSetAttribute(gemm_bf16_kernel<3>,
                         cudaFuncAttributeMaxDynamicSharedMemorySize, GSM_BYTES);
    cudaFuncSetAttribute(convproj_kernel,
                         cudaFuncAttributeMaxDynamicSharedMemorySize, CPSM_TOTAL);

    // 0) pre-split weights (3x blocked GEMM layout + x_proj fragment layout)
    split_blocked_kernel<<<dim3(DMODEL / 16, 1024 / 128), 256>>>(
        in_proj_w, w1h, w1l, DMODEL);
    split_blocked_kernel<<<dim3(DINNER / 16, DMODEL / 128), 256>>>(
        out_proj_w, w2h, w2l, DINNER);
    split_blocked_kernel<<<dim3(DMODEL / 16, NOUT / 128), 256>>>(
        dim_w, w3h, w3l, DMODEL);
    wxsplit_kernel<<<32, 192>>>(x_proj_w);

    // 1) xz = inputs @ in_proj_w^T  [32768 x 1024], silu on z half (bn>=4)
    gemm_bf16_kernel<3><<<dim3(1024 / 128, NROWS / 128), 256, GSM_BYTES>>>(
        inputs, w1h, w1l, xz, 1024, 256, nullptr);

    // 2) conv + silu + x_proj(MMA) + dt_proj, compact (delta, xc) pack
    convproj_kernel<<<NROWS / TOK, 512, CPSM_TOTAL>>>(conv_w, conv_b,
                                                      dt_proj_w, dt_proj_b);

    // 3) selective scan (v7: compact inputs, z from g_xz)
    scan_kernel<<<512, 128>>>(A_log, D_skip);

    // 4) t1 = silu(y @ out_proj_w^T)  [32768 x 256]
    gemm_bf16_kernel<1><<<dim3(256 / 128, NROWS / 128), 256, GSM_BYTES>>>(
        y, w2h, w2l, t1, 256, 512, nullptr);

    // 5) out = t1 @ dim_w^T + dim_b, + per-block partial sums
    gemm_bf16_kernel<2><<<dim3(256 / 128, NROWS / 128), 256, GSM_BYTES>>>(
        t1, w3h, w3l, out, 256, 256, dim_b);

    // 6) per-batch LayerNorm
    stats_kernel<<<1, 32>>>();
    norm_kernel<<<(NROWS * NOUT / 4) / 256, 256>>>(out, ln_w, ln_b);
}